// round 1
// baseline (speedup 1.0000x reference)
#include <cuda_runtime.h>
#include <math.h>

#define HDIM 96
#define WDIM 96
#define PIX  (HDIM*WDIM)     // 9216
#define NB   4
#define CINF 1024
#define CINT 512
#define DD   4
#define QD   9               // 2*DD+1
#define QQ   81
#define NPIX (NB*PIX)        // 36864

// Scratch in device globals (no allocation allowed).
__device__ float g_theta[(size_t)NPIX * CINT];        // NHWC [p][512]
__device__ float g_gphi [(size_t)NPIX * 2 * CINT];    // NHWC [p][1024]: [0:512)=g, [512:1024)=phi
__device__ float g_pw   [(size_t)NPIX * QQ];          // [p][81]
__device__ float g_y    [(size_t)NPIX * CINT];        // NHWC [p][512]

// ---------------------------------------------------------------------------
// SIMT fp32 GEMM: C[o][p] = sum_k A[o][k] * B[k][p]  (per batch n = blockIdx.z)
//   A rows split across A0/A1 at Asplit (for stacked w_g/w_phi).
//   BT=false: B is [K][PIX] (NCHW input, p contiguous)
//   BT=true : B is [PIX][K] (NHWC scratch, k contiguous)
//   RESID=false: write NHWC out[(n*PIX+p)*ldo + o] (+bias)
//   RESID=true : write NCHW out[(n*Mtot+o)*PIX + p] = acc + bias + resid[same]
// Tile 128x128x8, 256 threads, 8x8 microtile (split 4+4 halves).
// ---------------------------------------------------------------------------
template<bool BT, bool RESID>
__global__ __launch_bounds__(256, 2)
void gemm_k(const float* __restrict__ A0, const float* __restrict__ A1, int Asplit,
            const float* __restrict__ b0, const float* __restrict__ b1,
            const float* __restrict__ B, int K,
            float* __restrict__ out, int ldo,
            const float* __restrict__ resid, int Mtot)
{
    __shared__ float As[8][128];
    __shared__ float Bs[8][128];

    const int t  = threadIdx.x;
    const int tx = t & 15;
    const int ty = t >> 4;
    const int n     = blockIdx.z;
    const int pbase = blockIdx.x * 128;
    const int obase = blockIdx.y * 128;

    float acc[8][8];
    #pragma unroll
    for (int i = 0; i < 8; i++)
        #pragma unroll
        for (int j = 0; j < 8; j++) acc[i][j] = 0.f;

    // A-load mapping: thread -> (o = t>>1, k = (t&1)*4), float4 along k
    const int oa = obase + (t >> 1);
    const int ka = (t & 1) * 4;
    const float* arow = (oa < Asplit) ? (A0 + (size_t)oa * K)
                                      : (A1 + (size_t)(oa - Asplit) * K);

    // B-load mapping
    const float* Bbase;
    int kb, pb;
    if (BT) {
        pb = t >> 1; kb = (t & 1) * 4;
        Bbase = B + ((size_t)n * PIX + pbase + pb) * K;
    } else {
        kb = t >> 5; pb = (t & 31) * 4;
        Bbase = B + (size_t)n * K * PIX + (size_t)kb * PIX + pbase + pb;
    }

    for (int k0 = 0; k0 < K; k0 += 8) {
        float4 va = *(const float4*)(arow + k0 + ka);
        float4 vb;
        if (BT) vb = *(const float4*)(Bbase + k0 + kb);
        else    vb = *(const float4*)(Bbase + (size_t)k0 * PIX);

        __syncthreads();   // previous compute done reading smem
        As[ka + 0][t >> 1] = va.x;
        As[ka + 1][t >> 1] = va.y;
        As[ka + 2][t >> 1] = va.z;
        As[ka + 3][t >> 1] = va.w;
        if (BT) {
            Bs[kb + 0][pb] = vb.x;
            Bs[kb + 1][pb] = vb.y;
            Bs[kb + 2][pb] = vb.z;
            Bs[kb + 3][pb] = vb.w;
        } else {
            *(float4*)&Bs[kb][pb] = vb;
        }
        __syncthreads();

        #pragma unroll
        for (int kk = 0; kk < 8; kk++) {
            float4 a0 = *(const float4*)&As[kk][ty * 4];
            float4 a1 = *(const float4*)&As[kk][64 + ty * 4];
            float4 c0 = *(const float4*)&Bs[kk][tx * 4];
            float4 c1 = *(const float4*)&Bs[kk][64 + tx * 4];
            float ar[8] = {a0.x, a0.y, a0.z, a0.w, a1.x, a1.y, a1.z, a1.w};
            float br[8] = {c0.x, c0.y, c0.z, c0.w, c1.x, c1.y, c1.z, c1.w};
            #pragma unroll
            for (int i = 0; i < 8; i++)
                #pragma unroll
                for (int j = 0; j < 8; j++)
                    acc[i][j] += ar[i] * br[j];
        }
    }

    // epilogue
    int orow[8], pcol[8];
    float biasr[8];
    #pragma unroll
    for (int i = 0; i < 8; i++) {
        int ol = (i < 4) ? (ty * 4 + i) : (64 + ty * 4 + (i - 4));
        int pl = (i < 4) ? (tx * 4 + i) : (64 + tx * 4 + (i - 4));
        orow[i] = obase + ol;
        pcol[i] = pbase + pl;
        int o = orow[i];
        biasr[i] = (o < Asplit) ? b0[o] : b1[o - Asplit];
    }

    if (RESID) {
        #pragma unroll
        for (int i = 0; i < 8; i++) {
            const int o = orow[i];
            #pragma unroll
            for (int jg = 0; jg < 2; jg++) {
                const int p0 = pbase + jg * 64 + tx * 4;
                const size_t addr = ((size_t)n * Mtot + o) * PIX + p0;
                float4 r = *(const float4*)(resid + addr);
                float4 v;
                v.x = acc[i][jg * 4 + 0] + biasr[i] + r.x;
                v.y = acc[i][jg * 4 + 1] + biasr[i] + r.y;
                v.z = acc[i][jg * 4 + 2] + biasr[i] + r.z;
                v.w = acc[i][jg * 4 + 3] + biasr[i] + r.w;
                *(float4*)(out + addr) = v;
            }
        }
    } else {
        #pragma unroll
        for (int j = 0; j < 8; j++) {
            const size_t base = ((size_t)n * PIX + pcol[j]) * ldo + obase;
            #pragma unroll
            for (int ig = 0; ig < 2; ig++) {
                const int o0 = ig * 64 + ty * 4;
                float4 v;
                v.x = acc[ig * 4 + 0][j] + biasr[ig * 4 + 0];
                v.y = acc[ig * 4 + 1][j] + biasr[ig * 4 + 1];
                v.z = acc[ig * 4 + 2][j] + biasr[ig * 4 + 2];
                v.w = acc[ig * 4 + 3][j] + biasr[ig * 4 + 3];
                *(float4*)(out + base + o0) = v;
            }
        }
    }
}

// ---------------------------------------------------------------------------
// Correlation + softmax, fused. 16x16 pixel tile, thread = pixel, 81 fp32 accs.
// theta NHWC ld=512; phi lives in g_gphi at channel offset 512, ld=1024.
// pw[p][q] = softmax_q( (1/512)*(256/sqrt(96)) * sum_c theta[p,c]*phi[p+d(q),c] )
// ---------------------------------------------------------------------------
__global__ __launch_bounds__(256)
void corr_softmax_k(const float* __restrict__ theta, const float* __restrict__ gphi,
                    float* __restrict__ pw)
{
    __shared__ float th_s[256][12];   // 8 used, pad->12 for conflict-free LDS.128
    __shared__ float ph_s[576][12];   // 24x24 halo, 8 channels, pad->12

    const int t  = threadIdx.x;
    const int n  = blockIdx.z;
    const int h0 = blockIdx.y * 16;
    const int w0 = blockIdx.x * 16;
    const int ty = t >> 4, tx = t & 15;

    float acc[QQ];
    #pragma unroll
    for (int q = 0; q < QQ; q++) acc[q] = 0.f;

    for (int c0 = 0; c0 < CINT; c0 += 8) {
        // stage theta tile: 256 px * 2 float4
        #pragma unroll
        for (int r = 0; r < 2; r++) {
            int jj = t + r * 256;
            int pl = jj >> 1, half = jj & 1;
            int h = h0 + (pl >> 4), w = w0 + (pl & 15);
            float4 v = *(const float4*)(theta + ((size_t)n * PIX + h * WDIM + w) * CINT + c0 + half * 4);
            *(float4*)&th_s[pl][half * 4] = v;
        }
        // stage phi halo: 576 px * 2 float4 = 1152
        #pragma unroll
        for (int r = 0; r < 5; r++) {
            int jj = t + r * 256;
            if (jj < 1152) {
                int pl = jj >> 1, half = jj & 1;
                int hy = h0 + (pl / 24) - DD;
                int hx = w0 + (pl % 24) - DD;
                float4 v = make_float4(0.f, 0.f, 0.f, 0.f);
                if (hy >= 0 && hy < HDIM && hx >= 0 && hx < WDIM)
                    v = *(const float4*)(gphi + ((size_t)n * PIX + hy * WDIM + hx) * (2 * CINT)
                                         + CINT + c0 + half * 4);
                *(float4*)&ph_s[pl][half * 4] = v;
            }
        }
        __syncthreads();

        float4 t0 = *(const float4*)&th_s[t][0];
        float4 t1 = *(const float4*)&th_s[t][4];
        #pragma unroll
        for (int dy = 0; dy < QD; dy++) {
            #pragma unroll
            for (int dx = 0; dx < QD; dx++) {
                int hp = (ty + dy) * 24 + (tx + dx);
                float4 p0 = *(const float4*)&ph_s[hp][0];
                float4 p1 = *(const float4*)&ph_s[hp][4];
                float s = t0.x * p0.x + t0.y * p0.y + t0.z * p0.z + t0.w * p0.w
                        + t1.x * p1.x + t1.y * p1.y + t1.z * p1.z + t1.w * p1.w;
                acc[dy * QD + dx] += s;
            }
        }
        __syncthreads();
    }

    // fused softmax over q (scale = 256/(512*sqrt(96)))
    const float SC = 0.051031036307982884f;
    float m = -1e30f;
    #pragma unroll
    for (int q = 0; q < QQ; q++) m = fmaxf(m, acc[q] * SC);
    float s = 0.f;
    #pragma unroll
    for (int q = 0; q < QQ; q++) { acc[q] = expf(acc[q] * SC - m); s += acc[q]; }
    const float inv = 1.f / s;

    const size_t base = ((size_t)n * PIX + (h0 + ty) * WDIM + (w0 + tx)) * QQ;
    #pragma unroll
    for (int q = 0; q < QQ; q++) pw[base + q] = acc[q] * inv;
}

// ---------------------------------------------------------------------------
// Assemble: y[p][c] = sum_q pw[p][q] * g[p + d(q)][c]   (g = gphi lo half)
// 8x8 pixel tile, thread = (pixel, 4-channel group), 16-channel smem chunks.
// ---------------------------------------------------------------------------
__global__ __launch_bounds__(256)
void assemble_k(const float* __restrict__ pw, const float* __restrict__ gphi,
                float* __restrict__ y)
{
    __shared__ float pw_s[64][QQ];   // 20.7 KB
    __shared__ float g_s[256][20];   // 16 used, pad->20; 16x16 halo

    const int t  = threadIdx.x;
    const int n  = blockIdx.z;
    const int h0 = blockIdx.y * 8;
    const int w0 = blockIdx.x * 8;
    const int c4 = t & 3;
    const int px = t >> 2;           // 0..63
    const int py = px >> 3, pxx = px & 7;

    // load pw for the tile once
    for (int j = t; j < 64 * QQ; j += 256) {
        int pl = j / QQ, q = j % QQ;
        int h = h0 + (pl >> 3), w = w0 + (pl & 7);
        pw_s[pl][q] = pw[((size_t)n * PIX + h * WDIM + w) * QQ + q];
    }

    const size_t ybase = ((size_t)n * PIX + (h0 + py) * WDIM + (w0 + pxx)) * CINT + c4 * 4;

    for (int c0 = 0; c0 < CINT; c0 += 16) {
        // stage g halo chunk: 256 hp * 4 float4
        #pragma unroll
        for (int r = 0; r < 4; r++) {
            int j  = t + r * 256;
            int hp = j >> 2, cl = j & 3;
            int hy = h0 + (hp >> 4) - DD;
            int hx = w0 + (hp & 15) - DD;
            float4 v = make_float4(0.f, 0.f, 0.f, 0.f);
            if (hy >= 0 && hy < HDIM && hx >= 0 && hx < WDIM)
                v = *(const float4*)(gphi + ((size_t)n * PIX + hy * WDIM + hx) * (2 * CINT)
                                     + c0 + cl * 4);
            *(float4*)&g_s[hp][cl * 4] = v;
        }
        __syncthreads();

        float4 a = make_float4(0.f, 0.f, 0.f, 0.f);
        #pragma unroll
        for (int dy = 0; dy < QD; dy++) {
            #pragma unroll
            for (int dx = 0; dx < QD; dx++) {
                float wq = pw_s[px][dy * QD + dx];
                float4 gv = *(const float4*)&g_s[(py + dy) * 16 + (pxx + dx)][c4 * 4];
                a.x += wq * gv.x; a.y += wq * gv.y; a.z += wq * gv.z; a.w += wq * gv.w;
            }
        }
        *(float4*)(y + ybase + c0) = a;
        __syncthreads();
    }
}

// ---------------------------------------------------------------------------
extern "C" void kernel_launch(void* const* d_in, const int* in_sizes, int n_in,
                              void* d_out, int out_size)
{
    (void)in_sizes; (void)n_in; (void)out_size;
    const float* x       = (const float*)d_in[0];
    const float* x_ref   = (const float*)d_in[1];
    const float* w_g     = (const float*)d_in[2];
    const float* b_g     = (const float*)d_in[3];
    const float* w_theta = (const float*)d_in[4];
    const float* b_theta = (const float*)d_in[5];
    const float* w_phi   = (const float*)d_in[6];
    const float* b_phi   = (const float*)d_in[7];
    const float* w_out   = (const float*)d_in[8];
    const float* b_out   = (const float*)d_in[9];
    float* out = (float*)d_out;

    float *theta_d, *gphi_d, *pw_d, *y_d;
    cudaGetSymbolAddress((void**)&theta_d, g_theta);
    cudaGetSymbolAddress((void**)&gphi_d,  g_gphi);
    cudaGetSymbolAddress((void**)&pw_d,    g_pw);
    cudaGetSymbolAddress((void**)&y_d,     g_y);

    dim3 blk(256);

    // theta = w_theta @ x   -> NHWC [p][512]
    gemm_k<false, false><<<dim3(72, 4, NB), blk>>>(
        w_theta, w_theta, CINT, b_theta, b_theta,
        x, CINF, theta_d, CINT, nullptr, 0);

    // [g; phi] = [w_g; w_phi] @ x_ref -> NHWC [p][1024]
    gemm_k<false, false><<<dim3(72, 8, NB), blk>>>(
        w_g, w_phi, CINT, b_g, b_phi,
        x_ref, CINF, gphi_d, 2 * CINT, nullptr, 0);

    // correlation + softmax -> pw [p][81]
    corr_softmax_k<<<dim3(6, 6, NB), blk>>>(theta_d, gphi_d, pw_d);

    // assemble -> y NHWC [p][512]
    assemble_k<<<dim3(12, 12, NB), blk>>>(pw_d, gphi_d, y_d);

    // out = x + w_out @ y + b_out   (NCHW)
    gemm_k<true, true><<<dim3(72, 8, NB), blk>>>(
        w_out, w_out, CINF, b_out, b_out,
        y_d, CINT, out, 0, x, CINF);
}

// round 3
// speedup vs baseline: 1.8654x; 1.8654x over previous
#include <cuda_runtime.h>
#include <cuda_bf16.h>
#include <cstdint>
#include <math.h>

#define HDIM 96
#define WDIM 96
#define PIX  (HDIM*WDIM)     // 9216
#define NB   4
#define CINF 1024
#define CINT 512
#define DD   4
#define QD   9
#define QQ   81
#define NPIX (NB*PIX)        // 36864

// ------------------------- scratch (device globals) -------------------------
__device__ float g_theta[(size_t)NPIX * CINT];              // fp32 NHWC [p][512]
__device__ float g_gphi [(size_t)NPIX * 2 * CINT];          // fp32 NHWC [p][1024] (g|phi)
__device__ float g_pw   [(size_t)NPIX * QQ];                // [p][81]
__device__ __nv_bfloat16 g_xT [(size_t)NPIX * CINF];        // bf16 [p][1024]
__device__ __nv_bfloat16 g_xrT[(size_t)NPIX * CINF];        // bf16 [p][1024]
__device__ __nv_bfloat16 g_ybf[(size_t)NPIX * CINT];        // bf16 [p][512]
__device__ __nv_bfloat16 g_wth[(size_t)CINT * CINF];        // bf16 [512][1024]
__device__ __nv_bfloat16 g_wgp[(size_t)CINF * CINF];        // bf16 [1024][1024] (wg;wphi)
__device__ __nv_bfloat16 g_wo [(size_t)CINF * CINT];        // bf16 [1024][512]

// ------------------------- helpers ------------------------------------------
__device__ __forceinline__ uint32_t smem_u32(const void* p) {
    uint32_t a;
    asm("{ .reg .u64 t; cvta.to.shared.u64 t, %1; cvt.u32.u64 %0, t; }" : "=r"(a) : "l"(p));
    return a;
}
#define CP_ASYNC16(dst, src) \
    asm volatile("cp.async.cg.shared.global [%0], [%1], 16;" :: "r"(dst), "l"(src))
#define CP_COMMIT() asm volatile("cp.async.commit_group;" ::: "memory")
#define CP_WAIT(n)  asm volatile("cp.async.wait_group %0;" :: "n"(n) : "memory")

#define LDSM4(r, a) \
    asm volatile("ldmatrix.sync.aligned.m8n8.x4.shared.b16 {%0,%1,%2,%3}, [%4];" \
        : "=r"((r)[0]), "=r"((r)[1]), "=r"((r)[2]), "=r"((r)[3]) : "r"(a))

#define MMA16816(d, a, bb0, bb1) \
    asm volatile("mma.sync.aligned.m16n8k16.row.col.f32.bf16.bf16.f32 " \
        "{%0,%1,%2,%3},{%4,%5,%6,%7},{%8,%9},{%0,%1,%2,%3};" \
        : "+f"((d)[0]), "+f"((d)[1]), "+f"((d)[2]), "+f"((d)[3]) \
        : "r"((a)[0]), "r"((a)[1]), "r"((a)[2]), "r"((a)[3]), "r"(bb0), "r"(bb1))

// swizzled byte offset inside a [rows][32 bf16] tile (row = 64B = 4 x 16B chunks)
__device__ __forceinline__ uint32_t sw_off(int row, int ch) {
    return (uint32_t)(row * 64 + ((ch ^ ((row >> 1) & 3)) << 4));
}

// ------------------------- transpose + convert ------------------------------
// src [n][1024][PIX] fp32 -> dst [n][PIX][1024] bf16
__global__ void conv_tr_k(const float* __restrict__ src, __nv_bfloat16* __restrict__ dst)
{
    __shared__ float ts[32][33];
    const int tx = threadIdx.x, ty = threadIdx.y;
    const int p0 = blockIdx.x * 32, c0 = blockIdx.y * 32, n = blockIdx.z;
    #pragma unroll
    for (int r = 0; r < 4; r++) {
        int c = c0 + ty + r * 8;
        ts[ty + r * 8][tx] = src[((size_t)n * CINF + c) * PIX + p0 + tx];
    }
    __syncthreads();
    #pragma unroll
    for (int r = 0; r < 4; r++) {
        int p = p0 + ty + r * 8;
        dst[((size_t)n * PIX + p) * CINF + c0 + tx] = __float2bfloat16(ts[tx][ty + r * 8]);
    }
}

__global__ void cvt_k(const float* __restrict__ src, __nv_bfloat16* __restrict__ dst, int count)
{
    int i = blockIdx.x * 256 + threadIdx.x;
    if (i < count) dst[i] = __float2bfloat16(src[i]);
}

// ------------------------- HMMA (mma.sync) GEMM ------------------------------
// C[o][p] = sum_k A[o][k] * B[p][k]; A bf16 [M][K] K-major, B bf16 [n*PIX+p][K].
// Block tile 128(M) x 128(N) x 32(K), 3-stage cp.async pipeline, 8 warps (2x4),
// warp tile 64x32, m16n8k16 HMMA, fp32 accum.
// RESID=false: out fp32 NHWC out[(n*PIX+p)*ldo + o] = acc + bias
// RESID=true : out fp32 NCHW out[(n*CINF+o)*PIX + p] = acc + bias + resid[same]
template<bool RESID>
__global__ __launch_bounds__(256)
void mma_gemm(const __nv_bfloat16* __restrict__ A, const __nv_bfloat16* __restrict__ B,
              int K, const float* __restrict__ b0, const float* __restrict__ b1, int bsplit,
              float* __restrict__ out, int ldo, const float* __restrict__ resid)
{
    __shared__ char smem[3 * 16384];   // per stage: A 8KB | B 8KB

    const int t = threadIdx.x, lane = t & 31, wid = t >> 5;
    const int warp_m = wid >> 2;       // 0..1  (64 rows)
    const int warp_n = wid & 3;        // 0..3  (32 cols)
    const int n = blockIdx.z, pbase = blockIdx.x * 128, obase = blockIdx.y * 128;

    const __nv_bfloat16* Ab = A + (size_t)obase * K;
    const __nv_bfloat16* Bb = B + ((size_t)n * PIX + pbase) * K;
    const uint32_t sbase = smem_u32(smem);
    const int NC = K >> 5;

    float acc[4][4][4];
    #pragma unroll
    for (int mi = 0; mi < 4; mi++)
        #pragma unroll
        for (int ni = 0; ni < 4; ni++)
            #pragma unroll
            for (int r = 0; r < 4; r++) acc[mi][ni][r] = 0.f;

    auto issue = [&](int c) {
        const int k0 = c << 5;
        const uint32_t st = sbase + (c % 3) * 16384;
        #pragma unroll
        for (int i = 0; i < 2; i++) {
            int idx = t + i * 256;
            int row = idx >> 2, ch = idx & 3;
            CP_ASYNC16(st + sw_off(row, ch), Ab + (size_t)row * K + k0 + ch * 8);
        }
        #pragma unroll
        for (int i = 0; i < 2; i++) {
            int idx = t + i * 256;
            int row = idx >> 2, ch = idx & 3;
            CP_ASYNC16(st + 8192 + sw_off(row, ch), Bb + (size_t)row * K + k0 + ch * 8);
        }
        CP_COMMIT();
    };

    issue(0);
    if (NC > 1) issue(1);

    const int rl = lane & 15;        // ldmatrix row within 16
    const int cs = lane >> 4;        // ldmatrix 16B-chunk select

    for (int c = 0; c < NC; c++) {
        if (c < NC - 1) CP_WAIT(1); else CP_WAIT(0);
        __syncthreads();
        if (c + 2 < NC) issue(c + 2);

        const uint32_t stA = sbase + (c % 3) * 16384;
        const uint32_t stB = stA + 8192;

        #pragma unroll
        for (int kh = 0; kh < 2; kh++) {
            const int ch = 2 * kh + cs;
            uint32_t af[4][4], bf[2][4];
            #pragma unroll
            for (int mi = 0; mi < 4; mi++) {
                int row = warp_m * 64 + mi * 16 + rl;
                LDSM4(af[mi], stA + sw_off(row, ch));
            }
            #pragma unroll
            for (int g = 0; g < 2; g++) {
                int row = warp_n * 32 + g * 16 + rl;
                LDSM4(bf[g], stB + sw_off(row, ch));
            }
            #pragma unroll
            for (int mi = 0; mi < 4; mi++) {
                #pragma unroll
                for (int g = 0; g < 2; g++) {
                    MMA16816(acc[mi][2 * g + 0], af[mi], bf[g][0], bf[g][2]);
                    MMA16816(acc[mi][2 * g + 1], af[mi], bf[g][1], bf[g][3]);
                }
            }
        }
        __syncthreads();
    }

    // ---------------- epilogue ----------------
    if (!RESID) {
        #pragma unroll
        for (int mi = 0; mi < 4; mi++) {
            #pragma unroll
            for (int h = 0; h < 2; h++) {
                const int o = obase + warp_m * 64 + mi * 16 + (lane >> 2) + h * 8;
                const float bias = (o < bsplit) ? b0[o] : b1[o - bsplit];
                #pragma unroll
                for (int ni = 0; ni < 4; ni++) {
                    const int p = pbase + warp_n * 32 + ni * 8 + (lane & 3) * 2;
                    const size_t base = ((size_t)n * PIX + p) * ldo + o;
                    out[base]       = acc[mi][ni][2 * h + 0] + bias;
                    out[base + ldo] = acc[mi][ni][2 * h + 1] + bias;
                }
            }
        }
    } else {
        #pragma unroll
        for (int mi = 0; mi < 4; mi++) {
            #pragma unroll
            for (int h = 0; h < 2; h++) {
                const int o = obase + warp_m * 64 + mi * 16 + (lane >> 2) + h * 8;
                const float bias = b0[o];
                #pragma unroll
                for (int ni = 0; ni < 4; ni++) {
                    const int p = pbase + warp_n * 32 + ni * 8 + (lane & 3) * 2;
                    const size_t addr = ((size_t)n * CINF + o) * PIX + p;
                    float2 r = *(const float2*)(resid + addr);
                    float2 v;
                    v.x = acc[mi][ni][2 * h + 0] + bias + r.x;
                    v.y = acc[mi][ni][2 * h + 1] + bias + r.y;
                    *(float2*)(out + addr) = v;
                }
            }
        }
    }
}

// ------------------------- correlation + softmax ----------------------------
__global__ __launch_bounds__(256)
void corr_softmax_k(const float* __restrict__ theta, const float* __restrict__ gphi,
                    float* __restrict__ pw)
{
    __shared__ float th_s[256][12];
    __shared__ float ph_s[576][12];

    const int t  = threadIdx.x;
    const int n  = blockIdx.z;
    const int h0 = blockIdx.y * 16;
    const int w0 = blockIdx.x * 16;
    const int ty = t >> 4, tx = t & 15;

    float acc[QQ];
    #pragma unroll
    for (int q = 0; q < QQ; q++) acc[q] = 0.f;

    for (int c0 = 0; c0 < CINT; c0 += 8) {
        #pragma unroll
        for (int r = 0; r < 2; r++) {
            int jj = t + r * 256;
            int pl = jj >> 1, half = jj & 1;
            int h = h0 + (pl >> 4), w = w0 + (pl & 15);
            float4 v = *(const float4*)(theta + ((size_t)n * PIX + h * WDIM + w) * CINT + c0 + half * 4);
            *(float4*)&th_s[pl][half * 4] = v;
        }
        #pragma unroll
        for (int r = 0; r < 5; r++) {
            int jj = t + r * 256;
            if (jj < 1152) {
                int pl = jj >> 1, half = jj & 1;
                int hy = h0 + (pl / 24) - DD;
                int hx = w0 + (pl % 24) - DD;
                float4 v = make_float4(0.f, 0.f, 0.f, 0.f);
                if (hy >= 0 && hy < HDIM && hx >= 0 && hx < WDIM)
                    v = *(const float4*)(gphi + ((size_t)n * PIX + hy * WDIM + hx) * (2 * CINT)
                                         + CINT + c0 + half * 4);
                *(float4*)&ph_s[pl][half * 4] = v;
            }
        }
        __syncthreads();

        float4 t0 = *(const float4*)&th_s[t][0];
        float4 t1 = *(const float4*)&th_s[t][4];
        #pragma unroll
        for (int dy = 0; dy < QD; dy++) {
            #pragma unroll
            for (int dx = 0; dx < QD; dx++) {
                int hp = (ty + dy) * 24 + (tx + dx);
                float4 p0 = *(const float4*)&ph_s[hp][0];
                float4 p1 = *(const float4*)&ph_s[hp][4];
                float s = t0.x * p0.x + t0.y * p0.y + t0.z * p0.z + t0.w * p0.w
                        + t1.x * p1.x + t1.y * p1.y + t1.z * p1.z + t1.w * p1.w;
                acc[dy * QD + dx] += s;
            }
        }
        __syncthreads();
    }

    const float SC = 0.051031036307982884f;   // 256/(512*sqrt(96))
    float m = -1e30f;
    #pragma unroll
    for (int q = 0; q < QQ; q++) m = fmaxf(m, acc[q] * SC);
    float s = 0.f;
    #pragma unroll
    for (int q = 0; q < QQ; q++) { acc[q] = expf(acc[q] * SC - m); s += acc[q]; }
    const float inv = 1.f / s;

    const size_t base = ((size_t)n * PIX + (h0 + ty) * WDIM + (w0 + tx)) * QQ;
    #pragma unroll
    for (int q = 0; q < QQ; q++) pw[base + q] = acc[q] * inv;
}

// ------------------------- assemble (-> bf16 y) -----------------------------
__global__ __launch_bounds__(256)
void assemble_k(const float* __restrict__ pw, const float* __restrict__ gphi,
                __nv_bfloat16* __restrict__ y)
{
    __shared__ float pw_s[64][QQ];
    __shared__ float g_s[256][20];

    const int t  = threadIdx.x;
    const int n  = blockIdx.z;
    const int h0 = blockIdx.y * 8;
    const int w0 = blockIdx.x * 8;
    const int c4 = t & 3;
    const int px = t >> 2;
    const int py = px >> 3, pxx = px & 7;

    for (int j = t; j < 64 * QQ; j += 256) {
        int pl = j / QQ, q = j % QQ;
        int h = h0 + (pl >> 3), w = w0 + (pl & 7);
        pw_s[pl][q] = pw[((size_t)n * PIX + h * WDIM + w) * QQ + q];
    }

    const size_t ybase = ((size_t)n * PIX + (h0 + py) * WDIM + (w0 + pxx)) * CINT + c4 * 4;

    for (int c0 = 0; c0 < CINT; c0 += 16) {
        #pragma unroll
        for (int r = 0; r < 4; r++) {
            int j  = t + r * 256;
            int hp = j >> 2, cl = j & 3;
            int hy = h0 + (hp >> 4) - DD;
            int hx = w0 + (hp & 15) - DD;
            float4 v = make_float4(0.f, 0.f, 0.f, 0.f);
            if (hy >= 0 && hy < HDIM && hx >= 0 && hx < WDIM)
                v = *(const float4*)(gphi + ((size_t)n * PIX + hy * WDIM + hx) * (2 * CINT)
                                     + c0 + cl * 4);
            *(float4*)&g_s[hp][cl * 4] = v;
        }
        __syncthreads();

        float4 a = make_float4(0.f, 0.f, 0.f, 0.f);
        #pragma unroll
        for (int dy = 0; dy < QD; dy++) {
            #pragma unroll
            for (int dx = 0; dx < QD; dx++) {
                float wq = pw_s[px][dy * QD + dx];
                float4 gv = *(const float4*)&g_s[(py + dy) * 16 + (pxx + dx)][c4 * 4];
                a.x += wq * gv.x; a.y += wq * gv.y; a.z += wq * gv.z; a.w += wq * gv.w;
            }
        }
        __nv_bfloat162 lo = __floats2bfloat162_rn(a.x, a.y);
        __nv_bfloat162 hi = __floats2bfloat162_rn(a.z, a.w);
        uint2 pk;
        pk.x = *(uint32_t*)&lo;
        pk.y = *(uint32_t*)&hi;
        *(uint2*)(y + ybase + c0) = pk;
        __syncthreads();
    }
}

// ---------------------------------------------------------------------------
extern "C" void kernel_launch(void* const* d_in, const int* in_sizes, int n_in,
                              void* d_out, int out_size)
{
    (void)in_sizes; (void)n_in; (void)out_size;
    const float* x       = (const float*)d_in[0];
    const float* x_ref   = (const float*)d_in[1];
    const float* w_g     = (const float*)d_in[2];
    const float* b_g     = (const float*)d_in[3];
    const float* w_theta = (const float*)d_in[4];
    const float* b_theta = (const float*)d_in[5];
    const float* w_phi   = (const float*)d_in[6];
    const float* b_phi   = (const float*)d_in[7];
    const float* w_out   = (const float*)d_in[8];
    const float* b_out   = (const float*)d_in[9];
    float* out = (float*)d_out;

    float *theta_d, *gphi_d, *pw_d;
    __nv_bfloat16 *xT_d, *xrT_d, *ybf_d, *wth_d, *wgp_d, *wo_d;
    cudaGetSymbolAddress((void**)&theta_d, g_theta);
    cudaGetSymbolAddress((void**)&gphi_d,  g_gphi);
    cudaGetSymbolAddress((void**)&pw_d,    g_pw);
    cudaGetSymbolAddress((void**)&xT_d,    g_xT);
    cudaGetSymbolAddress((void**)&xrT_d,   g_xrT);
    cudaGetSymbolAddress((void**)&ybf_d,   g_ybf);
    cudaGetSymbolAddress((void**)&wth_d,   g_wth);
    cudaGetSymbolAddress((void**)&wgp_d,   g_wgp);
    cudaGetSymbolAddress((void**)&wo_d,    g_wo);

    // weight conversions (tiny)
    cvt_k<<<2048, 256>>>(w_theta, wth_d, CINT * CINF);
    cvt_k<<<2048, 256>>>(w_g,     wgp_d,              CINT * CINF);
    cvt_k<<<2048, 256>>>(w_phi,   wgp_d + (size_t)CINT * CINF, CINT * CINF);
    cvt_k<<<2048, 256>>>(w_out,   wo_d,  CINF * CINT);

    // transpose+convert inputs: NCHW fp32 -> [p][1024] bf16
    conv_tr_k<<<dim3(PIX / 32, CINF / 32, NB), dim3(32, 8)>>>(x,     xT_d);
    conv_tr_k<<<dim3(PIX / 32, CINF / 32, NB), dim3(32, 8)>>>(x_ref, xrT_d);

    // theta = w_theta @ x  -> fp32 NHWC [p][512]
    mma_gemm<false><<<dim3(72, 4, NB), 256>>>(
        wth_d, xT_d, CINF, b_theta, b_theta, CINT, theta_d, CINT, nullptr);

    // [g; phi] = [w_g; w_phi] @ x_ref -> fp32 NHWC [p][1024]
    mma_gemm<false><<<dim3(72, 8, NB), 256>>>(
        wgp_d, xrT_d, CINF, b_g, b_phi, CINT, gphi_d, 2 * CINT, nullptr);

    // correlation + softmax -> pw [p][81]
    corr_softmax_k<<<dim3(6, 6, NB), 256>>>(theta_d, gphi_d, pw_d);

    // assemble -> y bf16 [p][512]
    assemble_k<<<dim3(12, 12, NB), 256>>>(pw_d, gphi_d, ybf_d);

    // out = x + w_out @ y + b_out  (fp32 NCHW)
    mma_gemm<true><<<dim3(72, 8, NB), 256>>>(
        wo_d, ybf_d, CINT, b_out, b_out, CINF, out, 0, x);
}

// round 5
// speedup vs baseline: 5.2387x; 2.8083x over previous
#include <cuda_runtime.h>
#include <cuda_bf16.h>
#include <cstdint>
#include <math.h>

#define HDIM 96
#define WDIM 96
#define PIX  (HDIM*WDIM)     // 9216
#define NB   4
#define CINF 1024
#define CINT 512
#define DD   4
#define QD   9
#define QQ   81
#define NPIX (NB*PIX)        // 36864

// ------------------------- scratch (device globals) -------------------------
__device__ __nv_bfloat16 g_xT  [(size_t)NPIX * CINF];      // bf16 [p][1024]
__device__ __nv_bfloat16 g_xrT [(size_t)NPIX * CINF];      // bf16 [p][1024]
__device__ __nv_bfloat16 g_thb [(size_t)NPIX * CINT];      // bf16 theta NHWC [p][512]
__device__ __nv_bfloat16 g_gphib[(size_t)NPIX * 2 * CINT]; // bf16 g|phi NHWC [p][1024]
__device__ __nv_bfloat16 g_ybf [(size_t)NPIX * CINT];      // bf16 y NHWC [p][512]
__device__ __nv_bfloat16 g_wth [(size_t)CINT * CINF];
__device__ __nv_bfloat16 g_wgp [(size_t)CINF * CINF];      // (wg;wphi)
__device__ __nv_bfloat16 g_wo  [(size_t)CINF * CINT];

// ------------------------- helpers ------------------------------------------
__device__ __forceinline__ uint32_t smem_u32(const void* p) {
    uint32_t a;
    asm("{ .reg .u64 t; cvta.to.shared.u64 t, %1; cvt.u32.u64 %0, t; }" : "=r"(a) : "l"(p));
    return a;
}
#define CP_ASYNC16(dst, src) \
    asm volatile("cp.async.cg.shared.global [%0], [%1], 16;" :: "r"(dst), "l"(src))
#define CP_ASYNC16Z(dst, src, sz) \
    asm volatile("cp.async.cg.shared.global [%0], [%1], 16, %2;" :: "r"(dst), "l"(src), "r"(sz))
#define CP_COMMIT() asm volatile("cp.async.commit_group;" ::: "memory")
#define CP_WAIT(n)  asm volatile("cp.async.wait_group %0;" :: "n"(n) : "memory")

#define LDSM4(r, a) \
    asm volatile("ldmatrix.sync.aligned.m8n8.x4.shared.b16 {%0,%1,%2,%3}, [%4];" \
        : "=r"((r)[0]), "=r"((r)[1]), "=r"((r)[2]), "=r"((r)[3]) : "r"(a))
#define LDSM4T(r, a) \
    asm volatile("ldmatrix.sync.aligned.m8n8.x4.trans.shared.b16 {%0,%1,%2,%3}, [%4];" \
        : "=r"((r)[0]), "=r"((r)[1]), "=r"((r)[2]), "=r"((r)[3]) : "r"(a))

#define MMA16816(d, a, bb0, bb1) \
    asm volatile("mma.sync.aligned.m16n8k16.row.col.f32.bf16.bf16.f32 " \
        "{%0,%1,%2,%3},{%4,%5,%6,%7},{%8,%9},{%0,%1,%2,%3};" \
        : "+f"((d)[0]), "+f"((d)[1]), "+f"((d)[2]), "+f"((d)[3]) \
        : "r"((a)[0]), "r"((a)[1]), "r"((a)[2]), "r"((a)[3]), "r"(bb0), "r"(bb1))

// swizzled byte offset inside a [rows][32 bf16] tile (64B rows, 4 x 16B chunks)
__device__ __forceinline__ uint32_t sw_off(int row, int ch) {
    return (uint32_t)(row * 64 + ((ch ^ ((row >> 1) & 3)) << 4));
}

// ------------------------- transpose + convert ------------------------------
__global__ void conv_tr_k(const float* __restrict__ src, __nv_bfloat16* __restrict__ dst)
{
    __shared__ float ts[32][33];
    const int tx = threadIdx.x, ty = threadIdx.y;
    const int p0 = blockIdx.x * 32, c0 = blockIdx.y * 32, n = blockIdx.z;
    #pragma unroll
    for (int r = 0; r < 4; r++) {
        int c = c0 + ty + r * 8;
        ts[ty + r * 8][tx] = src[((size_t)n * CINF + c) * PIX + p0 + tx];
    }
    __syncthreads();
    #pragma unroll
    for (int r = 0; r < 4; r++) {
        int p = p0 + ty + r * 8;
        dst[((size_t)n * PIX + p) * CINF + c0 + tx] = __float2bfloat16(ts[tx][ty + r * 8]);
    }
}

// all four weight tensors are 524288 elements each
__global__ void cvt4_k(const float* __restrict__ s0, const float* __restrict__ s1,
                       const float* __restrict__ s2, const float* __restrict__ s3,
                       __nv_bfloat16* __restrict__ d0, __nv_bfloat16* __restrict__ d1,
                       __nv_bfloat16* __restrict__ d2, __nv_bfloat16* __restrict__ d3)
{
    int i = blockIdx.x * 256 + threadIdx.x;
    int seg = i >> 19, off = i & 524287;
    const float* s = (seg == 0) ? s0 : (seg == 1) ? s1 : (seg == 2) ? s2 : s3;
    __nv_bfloat16* d = (seg == 0) ? d0 : (seg == 1) ? d1 : (seg == 2) ? d2 : d3;
    d[off] = __float2bfloat16(s[off]);
}

// ------------------------- HMMA GEMM -----------------------------------------
// C[o][p] = sum_k A[o][k] * B[p][k]; 128x128x32 tile, 3-stage cp.async, 8 warps.
// RESID=false: out bf16 NHWC out[(n*PIX+p)*ldo + o] = acc + bias
// RESID=true : out fp32 NCHW out[(n*CINF+o)*PIX + p] = acc + bias + resid[same]
template<bool RESID>
__global__ __launch_bounds__(256)
void mma_gemm(const __nv_bfloat16* __restrict__ A, const __nv_bfloat16* __restrict__ B,
              int K, const float* __restrict__ b0, const float* __restrict__ b1, int bsplit,
              void* __restrict__ outv, int ldo, const float* __restrict__ resid)
{
    __shared__ char smem[3 * 16384];

    const int t = threadIdx.x, lane = t & 31, wid = t >> 5;
    const int warp_m = wid >> 2, warp_n = wid & 3;
    const int n = blockIdx.z, pbase = blockIdx.x * 128, obase = blockIdx.y * 128;

    const __nv_bfloat16* Ab = A + (size_t)obase * K;
    const __nv_bfloat16* Bb = B + ((size_t)n * PIX + pbase) * K;
    const uint32_t sbase = smem_u32(smem);
    const int NC = K >> 5;

    float acc[4][4][4];
    #pragma unroll
    for (int mi = 0; mi < 4; mi++)
        #pragma unroll
        for (int ni = 0; ni < 4; ni++)
            #pragma unroll
            for (int r = 0; r < 4; r++) acc[mi][ni][r] = 0.f;

    auto issue = [&](int c) {
        const int k0 = c << 5;
        const uint32_t st = sbase + (c % 3) * 16384;
        #pragma unroll
        for (int i = 0; i < 2; i++) {
            int idx = t + i * 256;
            int row = idx >> 2, ch = idx & 3;
            CP_ASYNC16(st + sw_off(row, ch), Ab + (size_t)row * K + k0 + ch * 8);
        }
        #pragma unroll
        for (int i = 0; i < 2; i++) {
            int idx = t + i * 256;
            int row = idx >> 2, ch = idx & 3;
            CP_ASYNC16(st + 8192 + sw_off(row, ch), Bb + (size_t)row * K + k0 + ch * 8);
        }
        CP_COMMIT();
    };

    issue(0);
    if (NC > 1) issue(1);

    const int rl = lane & 15, cs = lane >> 4;

    for (int c = 0; c < NC; c++) {
        if (c < NC - 1) CP_WAIT(1); else CP_WAIT(0);
        __syncthreads();
        if (c + 2 < NC) issue(c + 2);

        const uint32_t stA = sbase + (c % 3) * 16384;
        const uint32_t stB = stA + 8192;

        #pragma unroll
        for (int kh = 0; kh < 2; kh++) {
            const int ch = 2 * kh + cs;
            uint32_t af[4][4], bf[2][4];
            #pragma unroll
            for (int mi = 0; mi < 4; mi++)
                LDSM4(af[mi], stA + sw_off(warp_m * 64 + mi * 16 + rl, ch));
            #pragma unroll
            for (int g = 0; g < 2; g++)
                LDSM4(bf[g], stB + sw_off(warp_n * 32 + g * 16 + rl, ch));
            #pragma unroll
            for (int mi = 0; mi < 4; mi++)
                #pragma unroll
                for (int g = 0; g < 2; g++) {
                    MMA16816(acc[mi][2 * g + 0], af[mi], bf[g][0], bf[g][2]);
                    MMA16816(acc[mi][2 * g + 1], af[mi], bf[g][1], bf[g][3]);
                }
        }
        __syncthreads();
    }

    if (!RESID) {
        __nv_bfloat16* out = (__nv_bfloat16*)outv;
        #pragma unroll
        for (int mi = 0; mi < 4; mi++) {
            #pragma unroll
            for (int h = 0; h < 2; h++) {
                const int o = obase + warp_m * 64 + mi * 16 + (lane >> 2) + h * 8;
                const float bias = (o < bsplit) ? b0[o] : b1[o - bsplit];
                #pragma unroll
                for (int ni = 0; ni < 4; ni++) {
                    const int p = pbase + warp_n * 32 + ni * 8 + (lane & 3) * 2;
                    const size_t base = ((size_t)n * PIX + p) * ldo + o;
                    out[base]       = __float2bfloat16(acc[mi][ni][2 * h + 0] + bias);
                    out[base + ldo] = __float2bfloat16(acc[mi][ni][2 * h + 1] + bias);
                }
            }
        }
    } else {
        float* out = (float*)outv;
        #pragma unroll
        for (int mi = 0; mi < 4; mi++) {
            #pragma unroll
            for (int h = 0; h < 2; h++) {
                const int o = obase + warp_m * 64 + mi * 16 + (lane >> 2) + h * 8;
                const float bias = b0[o];
                #pragma unroll
                for (int ni = 0; ni < 4; ni++) {
                    const int p = pbase + warp_n * 32 + ni * 8 + (lane & 3) * 2;
                    const size_t addr = ((size_t)n * CINF + o) * PIX + p;
                    float2 r = *(const float2*)(resid + addr);
                    float2 v;
                    v.x = acc[mi][ni][2 * h + 0] + bias + r.x;
                    v.y = acc[mi][ni][2 * h + 1] + bias + r.y;
                    *(float2*)(out + addr) = v;
                }
            }
        }
    }
}

// ------------------------- fused corr + softmax + assemble -------------------
// Per 8x8 pixel tile (halo 16x16 = 256):
//   phase1: C[64][256] = theta_tile @ phi_halo^T  (tensor cores)
//   phase2: per-pixel softmax over its 81 halo cols -> PW bf16 [64][256] (+pad)
//   phase3: y[64][512] = PW @ g_halo              (tensor cores, B via ldmatrix.trans)
// SMEM: [0,33792) PW bf16 64x264 ; [33792,+68096) region X (stages / Cs) ; invs[64]
__global__ __launch_bounds__(256, 2)
void fused_attn_k(const __nv_bfloat16* __restrict__ theta,
                  const __nv_bfloat16* __restrict__ gphi,
                  __nv_bfloat16* __restrict__ y)
{
    extern __shared__ char smem[];
    char*  Xr   = smem + 33792;
    float* Cs   = (float*)Xr;                       // [64][266] fp32
    float* invs = (float*)(smem + 33792 + 68096);   // [64]

    const int t = threadIdx.x, lane = t & 31, wid = t >> 5;
    const int warp_m = wid >> 2, warp_n = wid & 3;  // 2 x 4
    const int rl = lane & 15, cs = lane >> 4;
    const int n = blockIdx.z, h0 = blockIdx.y * 8, w0 = blockIdx.x * 8;

    const uint32_t sbX  = smem_u32(Xr);
    const uint32_t sbPW = smem_u32(smem);

    float acc[2][8][4];
    #pragma unroll
    for (int a = 0; a < 2; a++)
        #pragma unroll
        for (int b = 0; b < 8; b++)
            #pragma unroll
            for (int c = 0; c < 4; c++) acc[a][b][c] = 0.f;

    // ---------------- phase 1: corr GEMM ----------------
    const int rowA = t >> 2, chA = t & 3;
    const __nv_bfloat16* thsrc =
        theta + ((size_t)n * PIX + (h0 + (rowA >> 3)) * WDIM + (w0 + (rowA & 7))) * CINT + chA * 8;

    const __nv_bfloat16* phsrc[4];
    uint32_t phok[4]; int phrow[4], phch[4];
    #pragma unroll
    for (int i = 0; i < 4; i++) {
        int idx = t + i * 256;
        int row = idx >> 2, ch = idx & 3;
        int hy = h0 + (row >> 4) - DD, hx = w0 + (row & 15) - DD;
        bool ok = (hy >= 0 && hy < HDIM && hx >= 0 && hx < WDIM);
        phrow[i] = row; phch[i] = ch; phok[i] = ok ? 16u : 0u;
        phsrc[i] = gphi + (ok ? (((size_t)n * PIX + hy * WDIM + hx) * 1024 + 512 + ch * 8) : 0);
    }

    auto issue1 = [&](int c) {
        const int c0 = c << 5;
        const uint32_t st = sbX + (c % 3) * 20480;
        CP_ASYNC16(st + sw_off(rowA, chA), thsrc + c0);
        #pragma unroll
        for (int i = 0; i < 4; i++)
            CP_ASYNC16Z(st + 4096 + sw_off(phrow[i], phch[i]),
                        phsrc[i] + (phok[i] ? c0 : 0), phok[i]);
        CP_COMMIT();
    };

    issue1(0); issue1(1);
    for (int c = 0; c < 16; c++) {
        if (c < 15) CP_WAIT(1); else CP_WAIT(0);
        __syncthreads();
        if (c + 2 < 16) issue1(c + 2);
        const uint32_t stA = sbX + (c % 3) * 20480;
        const uint32_t stB = stA + 4096;
        #pragma unroll
        for (int kh = 0; kh < 2; kh++) {
            const int ch = 2 * kh + cs;
            uint32_t af[2][4], bm[4][4];
            #pragma unroll
            for (int mi = 0; mi < 2; mi++)
                LDSM4(af[mi], stA + sw_off(warp_m * 32 + mi * 16 + rl, ch));
            #pragma unroll
            for (int nf = 0; nf < 4; nf++)
                LDSM4(bm[nf], stB + sw_off(warp_n * 64 + nf * 16 + rl, ch));
            #pragma unroll
            for (int mi = 0; mi < 2; mi++)
                #pragma unroll
                for (int nf = 0; nf < 4; nf++) {
                    MMA16816(acc[mi][2 * nf + 0], af[mi], bm[nf][0], bm[nf][2]);
                    MMA16816(acc[mi][2 * nf + 1], af[mi], bm[nf][1], bm[nf][3]);
                }
        }
    }
    __syncthreads();   // stages dead; write C to smem (overlays stage region)

    #pragma unroll
    for (int mi = 0; mi < 2; mi++)
        #pragma unroll
        for (int ni = 0; ni < 8; ni++) {
            const int r0  = warp_m * 32 + mi * 16 + (lane >> 2);
            const int col = warp_n * 64 + ni * 8 + 2 * (lane & 3);
            *(float2*)&Cs[(size_t)r0 * 266 + col]       = make_float2(acc[mi][ni][0], acc[mi][ni][1]);
            *(float2*)&Cs[(size_t)(r0 + 8) * 266 + col] = make_float2(acc[mi][ni][2], acc[mi][ni][3]);
        }
    __syncthreads();

    // ---------------- phase 2: softmax -> PW bf16 ----------------
    if (t < 64) {
        const int py = t >> 3, pxx = t & 7;
        uint32_t* pwz = (uint32_t*)(smem + t * 528);
        #pragma unroll 4
        for (int i = 0; i < 132; i++) pwz[i] = 0;
        const float SC = 0.051031036307982884f;   // 256/(512*sqrt(96))
        float m = -1e30f;
        #pragma unroll
        for (int dy = 0; dy < QD; dy++)
            #pragma unroll
            for (int dx = 0; dx < QD; dx++)
                m = fmaxf(m, Cs[(size_t)t * 266 + (py + dy) * 16 + pxx + dx] * SC);
        float s = 0.f;
        __nv_bfloat16* pwrow = (__nv_bfloat16*)(smem + t * 528);
        #pragma unroll
        for (int dy = 0; dy < QD; dy++)
            #pragma unroll
            for (int dx = 0; dx < QD; dx++) {
                const int col = (py + dy) * 16 + pxx + dx;
                float e = __expf(Cs[(size_t)t * 266 + col] * SC - m);
                s += e;
                pwrow[col] = __float2bfloat16(e);
            }
        invs[t] = 1.f / s;
    }
    __syncthreads();

    // ---------------- phase 3: assemble GEMM ----------------
    // Stage layout (FIXED): 32 halo rows x 512B (32 x 16B chunks = 256 channels),
    // swizzle chunk ^ (row & 7). Matches the ldmatrix.trans reads below.
    for (int half = 0; half < 2; half++) {
        const int cbase = half * 256;
        #pragma unroll
        for (int a = 0; a < 2; a++)
            #pragma unroll
            for (int b = 0; b < 8; b++)
                #pragma unroll
                for (int c = 0; c < 4; c++) acc[a][b][c] = 0.f;

        auto issue3 = [&](int kk) {
            const uint32_t st = sbX + (kk % 3) * 16384;
            #pragma unroll
            for (int i = 0; i < 4; i++) {
                int idx = t + i * 256;
                int row = idx >> 5, ch = idx & 31;
                int hp = kk * 32 + row;
                int hy = h0 + (hp >> 4) - DD, hx = w0 + (hp & 15) - DD;
                bool ok = (hy >= 0 && hy < HDIM && hx >= 0 && hx < WDIM);
                const __nv_bfloat16* src = gphi +
                    (ok ? (((size_t)n * PIX + hy * WDIM + hx) * 1024 + cbase + ch * 8) : 0);
                CP_ASYNC16Z(st + row * 512 + ((ch ^ (row & 7)) << 4), src, ok ? 16u : 0u);
            }
            CP_COMMIT();
        };

        issue3(0); issue3(1);
        for (int kk = 0; kk < 8; kk++) {
            if (kk < 7) CP_WAIT(1); else CP_WAIT(0);
            __syncthreads();
            if (kk + 2 < 8) issue3(kk + 2);
            const uint32_t st = sbX + (kk % 3) * 16384;
            #pragma unroll
            for (int kh = 0; kh < 2; kh++) {
                uint32_t af[2][4], bm[4][4];
                const int chunk = kk * 4 + kh * 2 + cs;
                #pragma unroll
                for (int mi = 0; mi < 2; mi++)
                    LDSM4(af[mi], sbPW + (warp_m * 32 + mi * 16 + rl) * 528 + chunk * 16);
                const int r = kh * 16 + rl;
                #pragma unroll
                for (int nf = 0; nf < 4; nf++) {
                    const int c16 = warp_n * 8 + nf * 2 + cs;
                    LDSM4T(bm[nf], st + r * 512 + ((c16 ^ (r & 7)) << 4));
                }
                #pragma unroll
                for (int mi = 0; mi < 2; mi++)
                    #pragma unroll
                    for (int nf = 0; nf < 4; nf++) {
                        MMA16816(acc[mi][2 * nf + 0], af[mi], bm[nf][0], bm[nf][1]);
                        MMA16816(acc[mi][2 * nf + 1], af[mi], bm[nf][2], bm[nf][3]);
                    }
            }
        }

        #pragma unroll
        for (int mi = 0; mi < 2; mi++)
            #pragma unroll
            for (int ni = 0; ni < 8; ni++) {
                const int r0 = warp_m * 32 + mi * 16 + (lane >> 2);
                const int cc = cbase + warp_n * 64 + ni * 8 + 2 * (lane & 3);
                #pragma unroll
                for (int hh = 0; hh < 2; hh++) {
                    const int px = r0 + hh * 8;
                    const float is = invs[px];
                    const size_t addr =
                        ((size_t)n * PIX + (h0 + (px >> 3)) * WDIM + (w0 + (px & 7))) * CINT + cc;
                    __nv_bfloat162 pk = __floats2bfloat162_rn(acc[mi][ni][2 * hh + 0] * is,
                                                              acc[mi][ni][2 * hh + 1] * is);
                    *(__nv_bfloat162*)(y + addr) = pk;
                }
            }
        __syncthreads();
    }
}

// ---------------------------------------------------------------------------
extern "C" void kernel_launch(void* const* d_in, const int* in_sizes, int n_in,
                              void* d_out, int out_size)
{
    (void)in_sizes; (void)n_in; (void)out_size;
    const float* x       = (const float*)d_in[0];
    const float* x_ref   = (const float*)d_in[1];
    const float* w_g     = (const float*)d_in[2];
    const float* b_g     = (const float*)d_in[3];
    const float* w_theta = (const float*)d_in[4];
    const float* b_theta = (const float*)d_in[5];
    const float* w_phi   = (const float*)d_in[6];
    const float* b_phi   = (const float*)d_in[7];
    const float* w_out   = (const float*)d_in[8];
    const float* b_out   = (const float*)d_in[9];
    float* out = (float*)d_out;

    __nv_bfloat16 *xT_d, *xrT_d, *thb_d, *gphib_d, *ybf_d, *wth_d, *wgp_d, *wo_d;
    cudaGetSymbolAddress((void**)&xT_d,    g_xT);
    cudaGetSymbolAddress((void**)&xrT_d,   g_xrT);
    cudaGetSymbolAddress((void**)&thb_d,   g_thb);
    cudaGetSymbolAddress((void**)&gphib_d, g_gphib);
    cudaGetSymbolAddress((void**)&ybf_d,   g_ybf);
    cudaGetSymbolAddress((void**)&wth_d,   g_wth);
    cudaGetSymbolAddress((void**)&wgp_d,   g_wgp);
    cudaGetSymbolAddress((void**)&wo_d,    g_wo);

    const int FUSED_SMEM = 33792 + 68096 + 256;   // 102144
    cudaFuncSetAttribute(fused_attn_k, cudaFuncAttributeMaxDynamicSharedMemorySize, FUSED_SMEM);

    // 1: all weight conversions in one launch
    cvt4_k<<<8192, 256>>>(w_theta, w_g, w_phi, w_out,
                          wth_d, wgp_d, wgp_d + (size_t)CINT * CINF, wo_d);

    // 2-3: transpose+convert inputs NCHW fp32 -> [p][1024] bf16
    conv_tr_k<<<dim3(PIX / 32, CINF / 32, NB), dim3(32, 8)>>>(x,     xT_d);
    conv_tr_k<<<dim3(PIX / 32, CINF / 32, NB), dim3(32, 8)>>>(x_ref, xrT_d);

    // 4: theta = w_theta @ x -> bf16 NHWC [p][512]
    mma_gemm<false><<<dim3(72, 4, NB), 256>>>(
        wth_d, xT_d, CINF, b_theta, b_theta, CINT, thb_d, CINT, nullptr);

    // 5: [g; phi] = [w_g; w_phi] @ x_ref -> bf16 NHWC [p][1024]
    mma_gemm<false><<<dim3(72, 8, NB), 256>>>(
        wgp_d, xrT_d, CINF, b_g, b_phi, CINT, gphib_d, 2 * CINT, nullptr);

    // 6: fused corr + softmax + assemble -> y bf16 [p][512]
    fused_attn_k<<<dim3(12, 12, NB), 256, FUSED_SMEM>>>(thb_d, gphib_d, ybf_d);

    // 7: out = x + w_out @ y + b_out (fp32 NCHW)
    mma_gemm<true><<<dim3(72, 8, NB), 256>>>(
        wo_d, ybf_d, CINT, b_out, b_out, CINF, out, 0, x);
}

// round 7
// speedup vs baseline: 5.6654x; 1.0815x over previous
#include <cuda_runtime.h>
#include <cuda_bf16.h>
#include <cstdint>
#include <math.h>

#define HDIM 96
#define WDIM 96
#define PIX  (HDIM*WDIM)     // 9216
#define NB   4
#define CINF 1024
#define CINT 512
#define DD   4
#define QD   9
#define QQ   81
#define NPIX (NB*PIX)        // 36864

// ------------------------- scratch (device globals) -------------------------
__device__ __nv_bfloat16 g_xT  [(size_t)NPIX * CINF];      // bf16 [p][1024]
__device__ __nv_bfloat16 g_xrT [(size_t)NPIX * CINF];      // bf16 [p][1024]
__device__ __nv_bfloat16 g_thb [(size_t)NPIX * CINT];      // bf16 theta NHWC [p][512]
__device__ __nv_bfloat16 g_gphib[(size_t)NPIX * 2 * CINT]; // bf16 g|phi NHWC [p][1024]
__device__ __nv_bfloat16 g_ybf [(size_t)NPIX * CINT];      // bf16 y NHWC [p][512]
__device__ __nv_bfloat16 g_wth [(size_t)CINT * CINF];
__device__ __nv_bfloat16 g_wgp [(size_t)CINF * CINF];      // (wg;wphi)
__device__ __nv_bfloat16 g_wo  [(size_t)CINF * CINT];

// ------------------------- helpers ------------------------------------------
__device__ __forceinline__ uint32_t smem_u32(const void* p) {
    uint32_t a;
    asm("{ .reg .u64 t; cvta.to.shared.u64 t, %1; cvt.u32.u64 %0, t; }" : "=r"(a) : "l"(p));
    return a;
}
#define CP_ASYNC16(dst, src) \
    asm volatile("cp.async.cg.shared.global [%0], [%1], 16;" :: "r"(dst), "l"(src))
#define CP_ASYNC16Z(dst, src, sz) \
    asm volatile("cp.async.cg.shared.global [%0], [%1], 16, %2;" :: "r"(dst), "l"(src), "r"(sz))
#define CP_COMMIT() asm volatile("cp.async.commit_group;" ::: "memory")
#define CP_WAIT(n)  asm volatile("cp.async.wait_group %0;" :: "n"(n) : "memory")

#define LDSM4(r, a) \
    asm volatile("ldmatrix.sync.aligned.m8n8.x4.shared.b16 {%0,%1,%2,%3}, [%4];" \
        : "=r"((r)[0]), "=r"((r)[1]), "=r"((r)[2]), "=r"((r)[3]) : "r"(a))
#define LDSM4T(r, a) \
    asm volatile("ldmatrix.sync.aligned.m8n8.x4.trans.shared.b16 {%0,%1,%2,%3}, [%4];" \
        : "=r"((r)[0]), "=r"((r)[1]), "=r"((r)[2]), "=r"((r)[3]) : "r"(a))

#define MMA16816(d, a, bb0, bb1) \
    asm volatile("mma.sync.aligned.m16n8k16.row.col.f32.bf16.bf16.f32 " \
        "{%0,%1,%2,%3},{%4,%5,%6,%7},{%8,%9},{%0,%1,%2,%3};" \
        : "+f"((d)[0]), "+f"((d)[1]), "+f"((d)[2]), "+f"((d)[3]) \
        : "r"((a)[0]), "r"((a)[1]), "r"((a)[2]), "r"((a)[3]), "r"(bb0), "r"(bb1))

// swizzled byte offset inside a [rows][32 bf16] tile (64B rows, 4 x 16B chunks)
__device__ __forceinline__ uint32_t sw_off(int row, int ch) {
    return (uint32_t)(row * 64 + ((ch ^ ((row >> 1) & 3)) << 4));
}

// ------------------------- transpose + convert ------------------------------
// src [n][1024][PIX] fp32 -> dst [n][PIX][1024] bf16. Tile 32p x 64c.
__global__ void conv_tr_k(const float* __restrict__ src, __nv_bfloat16* __restrict__ dst)
{
    __shared__ float ts[64][33];
    const int tx = threadIdx.x, ty = threadIdx.y;
    const int p0 = blockIdx.x * 32, c0 = blockIdx.y * 64, n = blockIdx.z;
    #pragma unroll
    for (int r = 0; r < 8; r++) {
        int cl = ty + r * 8;
        ts[cl][tx] = src[((size_t)n * CINF + c0 + cl) * PIX + p0 + tx];
    }
    __syncthreads();
    #pragma unroll
    for (int r = 0; r < 4; r++) {
        int pl = ty + r * 8;
        __nv_bfloat162 v = __floats2bfloat162_rn(ts[2 * tx][pl], ts[2 * tx + 1][pl]);
        *(__nv_bfloat162*)(dst + ((size_t)n * PIX + p0 + pl) * CINF + c0 + 2 * tx) = v;
    }
}

// all four weight tensors are 524288 elements each
__global__ void cvt4_k(const float* __restrict__ s0, const float* __restrict__ s1,
                       const float* __restrict__ s2, const float* __restrict__ s3,
                       __nv_bfloat16* __restrict__ d0, __nv_bfloat16* __restrict__ d1,
                       __nv_bfloat16* __restrict__ d2, __nv_bfloat16* __restrict__ d3)
{
    int i = blockIdx.x * 256 + threadIdx.x;
    int seg = i >> 19, off = i & 524287;
    const float* s = (seg == 0) ? s0 : (seg == 1) ? s1 : (seg == 2) ? s2 : s3;
    __nv_bfloat16* d = (seg == 0) ? d0 : (seg == 1) ? d1 : (seg == 2) ? d2 : d3;
    d[off] = __float2bfloat16(s[off]);
}

// ------------------------- merged projection GEMM ----------------------------
// blockIdx.y < 4 : theta = w_theta @ x   -> thb  [p][512]
// blockIdx.y >= 4: (g;phi) = wgp @ x_ref -> gphib [p][1024]
// 128x128x32 tile, 3-stage cp.async, 8 warps, SMEM-transposed bf16 epilogue.
__global__ __launch_bounds__(256)
void proj_gemm(const __nv_bfloat16* __restrict__ wth, const __nv_bfloat16* __restrict__ wgp,
               const __nv_bfloat16* __restrict__ xT, const __nv_bfloat16* __restrict__ xrT,
               const float* __restrict__ bth, const float* __restrict__ bg,
               const float* __restrict__ bphi,
               __nv_bfloat16* __restrict__ thb, __nv_bfloat16* __restrict__ gphib)
{
    __shared__ char smem[3 * 16384];

    const int t = threadIdx.x, lane = t & 31, wid = t >> 5;
    const int warp_m = wid >> 2, warp_n = wid & 3;
    const int n = blockIdx.z, pbase = blockIdx.x * 128;
    const int by = blockIdx.y;
    const bool th = (by < 4);
    const int obase = (th ? by : by - 4) * 128;
    const __nv_bfloat16* A  = th ? wth : wgp;
    const __nv_bfloat16* Bx = th ? xT : xrT;
    __nv_bfloat16* out = th ? thb : gphib;
    const int ldo = th ? CINT : 2 * CINT;
    const float* b0 = th ? bth : bg;
    const float* b1 = th ? bth : bphi;
    const int K = CINF, NC = K >> 5;

    const __nv_bfloat16* Ab = A + (size_t)obase * K;
    const __nv_bfloat16* Bb = Bx + ((size_t)n * PIX + pbase) * K;
    const uint32_t sbase = smem_u32(smem);

    float acc[4][4][4];
    #pragma unroll
    for (int mi = 0; mi < 4; mi++)
        #pragma unroll
        for (int ni = 0; ni < 4; ni++)
            #pragma unroll
            for (int r = 0; r < 4; r++) acc[mi][ni][r] = 0.f;

    auto issue = [&](int c) {
        const int k0 = c << 5;
        const uint32_t st = sbase + (c % 3) * 16384;
        #pragma unroll
        for (int i = 0; i < 2; i++) {
            int idx = t + i * 256;
            int row = idx >> 2, ch = idx & 3;
            CP_ASYNC16(st + sw_off(row, ch), Ab + (size_t)row * K + k0 + ch * 8);
        }
        #pragma unroll
        for (int i = 0; i < 2; i++) {
            int idx = t + i * 256;
            int row = idx >> 2, ch = idx & 3;
            CP_ASYNC16(st + 8192 + sw_off(row, ch), Bb + (size_t)row * K + k0 + ch * 8);
        }
        CP_COMMIT();
    };

    issue(0); issue(1);
    const int rl = lane & 15, cs = lane >> 4;

    for (int c = 0; c < NC; c++) {
        if (c < NC - 1) CP_WAIT(1); else CP_WAIT(0);
        __syncthreads();
        if (c + 2 < NC) issue(c + 2);

        const uint32_t stA = sbase + (c % 3) * 16384;
        const uint32_t stB = stA + 8192;
        #pragma unroll
        for (int kh = 0; kh < 2; kh++) {
            const int ch = 2 * kh + cs;
            uint32_t af[4][4], bf[2][4];
            #pragma unroll
            for (int mi = 0; mi < 4; mi++)
                LDSM4(af[mi], stA + sw_off(warp_m * 64 + mi * 16 + rl, ch));
            #pragma unroll
            for (int g = 0; g < 2; g++)
                LDSM4(bf[g], stB + sw_off(warp_n * 32 + g * 16 + rl, ch));
            #pragma unroll
            for (int mi = 0; mi < 4; mi++)
                #pragma unroll
                for (int g = 0; g < 2; g++) {
                    MMA16816(acc[mi][2 * g + 0], af[mi], bf[g][0], bf[g][2]);
                    MMA16816(acc[mi][2 * g + 1], af[mi], bf[g][1], bf[g][3]);
                }
        }
    }

    // epilogue: transpose via SMEM -> coalesced bf16 NHWC rows
    __syncthreads();
    __nv_bfloat16* S = (__nv_bfloat16*)smem;   // [128 p][136 o]
    #pragma unroll
    for (int mi = 0; mi < 4; mi++) {
        #pragma unroll
        for (int h = 0; h < 2; h++) {
            const int ol = warp_m * 64 + mi * 16 + (lane >> 2) + h * 8;
            const int og = obase + ol;
            const float bias = (og < CINT) ? b0[og] : b1[og - CINT];
            #pragma unroll
            for (int ni = 0; ni < 4; ni++) {
                const int pl = warp_n * 32 + ni * 8 + (lane & 3) * 2;
                S[(size_t)pl * 136 + ol]       = __float2bfloat16(acc[mi][ni][2 * h + 0] + bias);
                S[(size_t)(pl + 1) * 136 + ol] = __float2bfloat16(acc[mi][ni][2 * h + 1] + bias);
            }
        }
    }
    __syncthreads();
    #pragma unroll
    for (int s = 0; s < 16; s++) {
        const int pl = s * 8 + wid;
        uint2 v = *(uint2*)&S[(size_t)pl * 136 + lane * 4];
        *(uint2*)(out + ((size_t)n * PIX + pbase + pl) * ldo + obase + lane * 4) = v;
    }
}

// ------------------------- final GEMM (residual, fp32 NCHW) ------------------
// out[(n*CINF+o)*PIX + p] = sum_k wo[o][k]*y[p][k] + b[o] + resid[same]
__global__ __launch_bounds__(256)
void final_gemm(const __nv_bfloat16* __restrict__ A, const __nv_bfloat16* __restrict__ B,
                const float* __restrict__ b0, float* __restrict__ out,
                const float* __restrict__ resid)
{
    __shared__ char smem[3 * 16384];

    const int t = threadIdx.x, lane = t & 31, wid = t >> 5;
    const int warp_m = wid >> 2, warp_n = wid & 3;
    const int n = blockIdx.z, pbase = blockIdx.x * 128, obase = blockIdx.y * 128;
    const int K = CINT, NC = K >> 5;

    const __nv_bfloat16* Ab = A + (size_t)obase * K;
    const __nv_bfloat16* Bb = B + ((size_t)n * PIX + pbase) * K;
    const uint32_t sbase = smem_u32(smem);

    float acc[4][4][4];
    #pragma unroll
    for (int mi = 0; mi < 4; mi++)
        #pragma unroll
        for (int ni = 0; ni < 4; ni++)
            #pragma unroll
            for (int r = 0; r < 4; r++) acc[mi][ni][r] = 0.f;

    auto issue = [&](int c) {
        const int k0 = c << 5;
        const uint32_t st = sbase + (c % 3) * 16384;
        #pragma unroll
        for (int i = 0; i < 2; i++) {
            int idx = t + i * 256;
            int row = idx >> 2, ch = idx & 3;
            CP_ASYNC16(st + sw_off(row, ch), Ab + (size_t)row * K + k0 + ch * 8);
        }
        #pragma unroll
        for (int i = 0; i < 2; i++) {
            int idx = t + i * 256;
            int row = idx >> 2, ch = idx & 3;
            CP_ASYNC16(st + 8192 + sw_off(row, ch), Bb + (size_t)row * K + k0 + ch * 8);
        }
        CP_COMMIT();
    };

    issue(0); issue(1);
    const int rl = lane & 15, cs = lane >> 4;

    for (int c = 0; c < NC; c++) {
        if (c < NC - 1) CP_WAIT(1); else CP_WAIT(0);
        __syncthreads();
        if (c + 2 < NC) issue(c + 2);

        const uint32_t stA = sbase + (c % 3) * 16384;
        const uint32_t stB = stA + 8192;
        #pragma unroll
        for (int kh = 0; kh < 2; kh++) {
            const int ch = 2 * kh + cs;
            uint32_t af[4][4], bf[2][4];
            #pragma unroll
            for (int mi = 0; mi < 4; mi++)
                LDSM4(af[mi], stA + sw_off(warp_m * 64 + mi * 16 + rl, ch));
            #pragma unroll
            for (int g = 0; g < 2; g++)
                LDSM4(bf[g], stB + sw_off(warp_n * 32 + g * 16 + rl, ch));
            #pragma unroll
            for (int mi = 0; mi < 4; mi++)
                #pragma unroll
                for (int g = 0; g < 2; g++) {
                    MMA16816(acc[mi][2 * g + 0], af[mi], bf[g][0], bf[g][2]);
                    MMA16816(acc[mi][2 * g + 1], af[mi], bf[g][1], bf[g][3]);
                }
        }
    }

    // epilogue: stage to SMEM, then fully-coalesced resid add + store
    float* Es = (float*)smem;   // [64 o][132 p]
    #pragma unroll
    for (int og = 0; og < 2; og++) {
        __syncthreads();
        if (warp_m == og) {
            #pragma unroll
            for (int mi = 0; mi < 4; mi++)
                #pragma unroll
                for (int h = 0; h < 2; h++) {
                    const int row = mi * 16 + (lane >> 2) + h * 8;
                    #pragma unroll
                    for (int ni = 0; ni < 4; ni++) {
                        const int col = warp_n * 32 + ni * 8 + (lane & 3) * 2;
                        Es[(size_t)row * 132 + col]     = acc[mi][ni][2 * h + 0];
                        Es[(size_t)row * 132 + col + 1] = acc[mi][ni][2 * h + 1];
                    }
                }
        }
        __syncthreads();
        #pragma unroll
        for (int s = 0; s < 8; s++) {
            const int row = s * 8 + wid;
            const int o = obase + og * 64 + row;
            const size_t addr = ((size_t)n * CINF + o) * PIX + pbase + lane * 4;
            float4 e = *(float4*)&Es[(size_t)row * 132 + lane * 4];
            float4 r = *(const float4*)(resid + addr);
            const float bias = b0[o];
            float4 v;
            v.x = e.x + bias + r.x; v.y = e.y + bias + r.y;
            v.z = e.z + bias + r.z; v.w = e.w + bias + r.w;
            *(float4*)(out + addr) = v;
        }
    }
}

// ------------------------- fused corr + softmax + assemble -------------------
// Per 8x8 pixel tile (halo 16x16 = 256):
//   phase1: C[64][256] = theta_tile @ phi_halo^T  (tensor cores)
//   phase2: per-pixel softmax over its 81 halo cols -> PW bf16 [64][256] (+pad)
//   phase3: y[64][512] = PW @ g_halo              (tensor cores, B via ldmatrix.trans)
__global__ __launch_bounds__(256, 2)
void fused_attn_k(const __nv_bfloat16* __restrict__ theta,
                  const __nv_bfloat16* __restrict__ gphi,
                  __nv_bfloat16* __restrict__ y)
{
    extern __shared__ char smem[];
    char*  Xr   = smem + 33792;
    float* Cs   = (float*)Xr;                       // [64][266] fp32
    float* invs = (float*)(smem + 33792 + 68096);   // [64]

    const int t = threadIdx.x, lane = t & 31, wid = t >> 5;
    const int warp_m = wid >> 2, warp_n = wid & 3;  // 2 x 4
    const int rl = lane & 15, cs = lane >> 4;
    const int n = blockIdx.z, h0 = blockIdx.y * 8, w0 = blockIdx.x * 8;

    const uint32_t sbX  = smem_u32(Xr);
    const uint32_t sbPW = smem_u32(smem);

    float acc[2][8][4];
    #pragma unroll
    for (int a = 0; a < 2; a++)
        #pragma unroll
        for (int b = 0; b < 8; b++)
            #pragma unroll
            for (int c = 0; c < 4; c++) acc[a][b][c] = 0.f;

    // ---------------- phase 1: corr GEMM ----------------
    const int rowA = t >> 2, chA = t & 3;
    const __nv_bfloat16* thsrc =
        theta + ((size_t)n * PIX + (h0 + (rowA >> 3)) * WDIM + (w0 + (rowA & 7))) * CINT + chA * 8;

    const __nv_bfloat16* phsrc[4];
    uint32_t phok[4]; int phrow[4], phch[4];
    #pragma unroll
    for (int i = 0; i < 4; i++) {
        int idx = t + i * 256;
        int row = idx >> 2, ch = idx & 3;
        int hy = h0 + (row >> 4) - DD, hx = w0 + (row & 15) - DD;
        bool ok = (hy >= 0 && hy < HDIM && hx >= 0 && hx < WDIM);
        phrow[i] = row; phch[i] = ch; phok[i] = ok ? 16u : 0u;
        phsrc[i] = gphi + (ok ? (((size_t)n * PIX + hy * WDIM + hx) * 1024 + 512 + ch * 8) : 0);
    }

    auto issue1 = [&](int c) {
        const int c0 = c << 5;
        const uint32_t st = sbX + (c % 3) * 20480;
        CP_ASYNC16(st + sw_off(rowA, chA), thsrc + c0);
        #pragma unroll
        for (int i = 0; i < 4; i++)
            CP_ASYNC16Z(st + 4096 + sw_off(phrow[i], phch[i]),
                        phsrc[i] + (phok[i] ? c0 : 0), phok[i]);
        CP_COMMIT();
    };

    issue1(0); issue1(1);
    for (int c = 0; c < 16; c++) {
        if (c < 15) CP_WAIT(1); else CP_WAIT(0);
        __syncthreads();
        if (c + 2 < 16) issue1(c + 2);
        const uint32_t stA = sbX + (c % 3) * 20480;
        const uint32_t stB = stA + 4096;
        #pragma unroll
        for (int kh = 0; kh < 2; kh++) {
            const int ch = 2 * kh + cs;
            uint32_t af[2][4], bm[4][4];
            #pragma unroll
            for (int mi = 0; mi < 2; mi++)
                LDSM4(af[mi], stA + sw_off(warp_m * 32 + mi * 16 + rl, ch));
            #pragma unroll
            for (int nf = 0; nf < 4; nf++)
                LDSM4(bm[nf], stB + sw_off(warp_n * 64 + nf * 16 + rl, ch));
            #pragma unroll
            for (int mi = 0; mi < 2; mi++)
                #pragma unroll
                for (int nf = 0; nf < 4; nf++) {
                    MMA16816(acc[mi][2 * nf + 0], af[mi], bm[nf][0], bm[nf][2]);
                    MMA16816(acc[mi][2 * nf + 1], af[mi], bm[nf][1], bm[nf][3]);
                }
        }
    }
    __syncthreads();   // stages dead; write C to smem (overlays stage region)

    #pragma unroll
    for (int mi = 0; mi < 2; mi++)
        #pragma unroll
        for (int ni = 0; ni < 8; ni++) {
            const int r0  = warp_m * 32 + mi * 16 + (lane >> 2);
            const int col = warp_n * 64 + ni * 8 + 2 * (lane & 3);
            *(float2*)&Cs[(size_t)r0 * 266 + col]       = make_float2(acc[mi][ni][0], acc[mi][ni][1]);
            *(float2*)&Cs[(size_t)(r0 + 8) * 266 + col] = make_float2(acc[mi][ni][2], acc[mi][ni][3]);
        }
    __syncthreads();

    // ---------------- phase 2: softmax -> PW bf16 ----------------
    if (t < 64) {
        const int py = t >> 3, pxx = t & 7;
        uint32_t* pwz = (uint32_t*)(smem + t * 528);
        #pragma unroll 4
        for (int i = 0; i < 132; i++) pwz[i] = 0;
        const float SC = 0.051031036307982884f;   // 256/(512*sqrt(96))
        float m = -1e30f;
        #pragma unroll
        for (int dy = 0; dy < QD; dy++)
            #pragma unroll
            for (int dx = 0; dx < QD; dx++)
                m = fmaxf(m, Cs[(size_t)t * 266 + (py + dy) * 16 + pxx + dx] * SC);
        float s = 0.f;
        __nv_bfloat16* pwrow = (__nv_bfloat16*)(smem + t * 528);
        #pragma unroll
        for (int dy = 0; dy < QD; dy++)
            #pragma unroll
            for (int dx = 0; dx < QD; dx++) {
                const int col = (py + dy) * 16 + pxx + dx;
                float e = __expf(Cs[(size_t)t * 266 + col] * SC - m);
                s += e;
                pwrow[col] = __float2bfloat16(e);
            }
        invs[t] = 1.f / s;
    }
    __syncthreads();

    // ---------------- phase 3: assemble GEMM ----------------
    // Stage: 32 halo rows x 512B (32 x 16B chunks), swizzle chunk ^ (row & 7).
    for (int half = 0; half < 2; half++) {
        const int cbase = half * 256;
        #pragma unroll
        for (int a = 0; a < 2; a++)
            #pragma unroll
            for (int b = 0; b < 8; b++)
                #pragma unroll
                for (int c = 0; c < 4; c++) acc[a][b][c] = 0.f;

        auto issue3 = [&](int kk) {
            const uint32_t st = sbX + (kk % 3) * 16384;
            #pragma unroll
            for (int i = 0; i < 4; i++) {
                int idx = t + i * 256;
                int row = idx >> 5, ch = idx & 31;
                int hp = kk * 32 + row;
                int hy = h0 + (hp >> 4) - DD, hx = w0 + (hp & 15) - DD;
                bool ok = (hy >= 0 && hy < HDIM && hx >= 0 && hx < WDIM);
                const __nv_bfloat16* src = gphi +
                    (ok ? (((size_t)n * PIX + hy * WDIM + hx) * 1024 + cbase + ch * 8) : 0);
                CP_ASYNC16Z(st + row * 512 + ((ch ^ (row & 7)) << 4), src, ok ? 16u : 0u);
            }
            CP_COMMIT();
        };

        issue3(0); issue3(1);
        for (int kk = 0; kk < 8; kk++) {
            if (kk < 7) CP_WAIT(1); else CP_WAIT(0);
            __syncthreads();
            if (kk + 2 < 8) issue3(kk + 2);
            const uint32_t st = sbX + (kk % 3) * 16384;
            #pragma unroll
            for (int kh = 0; kh < 2; kh++) {
                uint32_t af[2][4], bm[4][4];
                const int chunk = kk * 4 + kh * 2 + cs;
                #pragma unroll
                for (int mi = 0; mi < 2; mi++)
                    LDSM4(af[mi], sbPW + (warp_m * 32 + mi * 16 + rl) * 528 + chunk * 16);
                const int r = kh * 16 + rl;
                #pragma unroll
                for (int nf = 0; nf < 4; nf++) {
                    const int c16 = warp_n * 8 + nf * 2 + cs;
                    LDSM4T(bm[nf], st + r * 512 + ((c16 ^ (r & 7)) << 4));
                }
                #pragma unroll
                for (int mi = 0; mi < 2; mi++)
                    #pragma unroll
                    for (int nf = 0; nf < 4; nf++) {
                        MMA16816(acc[mi][2 * nf + 0], af[mi], bm[nf][0], bm[nf][1]);
                        MMA16816(acc[mi][2 * nf + 1], af[mi], bm[nf][2], bm[nf][3]);
                    }
            }
        }

        #pragma unroll
        for (int mi = 0; mi < 2; mi++)
            #pragma unroll
            for (int ni = 0; ni < 8; ni++) {
                const int r0 = warp_m * 32 + mi * 16 + (lane >> 2);
                const int cc = cbase + warp_n * 64 + ni * 8 + 2 * (lane & 3);
                #pragma unroll
                for (int hh = 0; hh < 2; hh++) {
                    const int px = r0 + hh * 8;
                    const float is = invs[px];
                    const size_t addr =
                        ((size_t)n * PIX + (h0 + (px >> 3)) * WDIM + (w0 + (px & 7))) * CINT + cc;
                    __nv_bfloat162 pk = __floats2bfloat162_rn(acc[mi][ni][2 * hh + 0] * is,
                                                              acc[mi][ni][2 * hh + 1] * is);
                    *(__nv_bfloat162*)(y + addr) = pk;
                }
            }
        __syncthreads();
    }
}

// ---------------------------------------------------------------------------
extern "C" void kernel_launch(void* const* d_in, const int* in_sizes, int n_in,
                              void* d_out, int out_size)
{
    (void)in_sizes; (void)n_in; (void)out_size;
    const float* x       = (const float*)d_in[0];
    const float* x_ref   = (const float*)d_in[1];
    const float* w_g     = (const float*)d_in[2];
    const float* b_g     = (const float*)d_in[3];
    const float* w_theta = (const float*)d_in[4];
    const float* b_theta = (const float*)d_in[5];
    const float* w_phi   = (const float*)d_in[6];
    const float* b_phi   = (const float*)d_in[7];
    const float* w_out   = (const float*)d_in[8];
    const float* b_out   = (const float*)d_in[9];
    float* out = (float*)d_out;

    __nv_bfloat16 *xT_d, *xrT_d, *thb_d, *gphib_d, *ybf_d, *wth_d, *wgp_d, *wo_d;
    cudaGetSymbolAddress((void**)&xT_d,    g_xT);
    cudaGetSymbolAddress((void**)&xrT_d,   g_xrT);
    cudaGetSymbolAddress((void**)&thb_d,   g_thb);
    cudaGetSymbolAddress((void**)&gphib_d, g_gphib);
    cudaGetSymbolAddress((void**)&ybf_d,   g_ybf);
    cudaGetSymbolAddress((void**)&wth_d,   g_wth);
    cudaGetSymbolAddress((void**)&wgp_d,   g_wgp);
    cudaGetSymbolAddress((void**)&wo_d,    g_wo);

    const int FUSED_SMEM = 33792 + 68096 + 256;   // 102144
    cudaFuncSetAttribute(fused_attn_k, cudaFuncAttributeMaxDynamicSharedMemorySize, FUSED_SMEM);

    // 1: all weight conversions in one launch
    cvt4_k<<<8192, 256>>>(w_theta, w_g, w_phi, w_out,
                          wth_d, wgp_d, wgp_d + (size_t)CINT * CINF, wo_d);

    // 2-3: transpose+convert inputs NCHW fp32 -> [p][1024] bf16
    conv_tr_k<<<dim3(PIX / 32, CINF / 64, NB), dim3(32, 8)>>>(x,     xT_d);
    conv_tr_k<<<dim3(PIX / 32, CINF / 64, NB), dim3(32, 8)>>>(x_ref, xrT_d);

    // 4: merged theta + (g;phi) projections -> bf16 NHWC
    proj_gemm<<<dim3(72, 12, NB), 256>>>(
        wth_d, wgp_d, xT_d, xrT_d, b_theta, b_g, b_phi, thb_d, gphib_d);

    // 5: fused corr + softmax + assemble -> y bf16 [p][512]
    fused_attn_k<<<dim3(12, 12, NB), 256, FUSED_SMEM>>>(thb_d, gphib_d, ybf_d);

    // 6: out = x + w_out @ y + b_out (fp32 NCHW)
    final_gemm<<<dim3(72, 8, NB), 256>>>(wo_d, ybf_d, b_out, out, x);
}

// round 8
// speedup vs baseline: 6.4043x; 1.1304x over previous
#include <cuda_runtime.h>
#include <cuda_bf16.h>
#include <cstdint>
#include <math.h>

#define HDIM 96
#define WDIM 96
#define PIX  (HDIM*WDIM)     // 9216
#define NB   4
#define CINF 1024
#define CINT 512
#define DD   4
#define QD   9
#define QQ   81
#define NPIX (NB*PIX)        // 36864

// ------------------------- scratch (device globals) -------------------------
__device__ __nv_bfloat16 g_xT  [(size_t)NPIX * CINF];      // bf16 [p][1024]
__device__ __nv_bfloat16 g_xrT [(size_t)NPIX * CINF];      // bf16 [p][1024]
__device__ __nv_bfloat16 g_thb [(size_t)NPIX * CINT];      // bf16 theta NHWC [p][512]
__device__ __nv_bfloat16 g_gphib[(size_t)NPIX * 2 * CINT]; // bf16 g|phi NHWC [p][1024]
__device__ __nv_bfloat16 g_ybf [(size_t)NPIX * CINT];      // bf16 y NHWC [p][512]
__device__ __nv_bfloat16 g_wth [(size_t)CINT * CINF];
__device__ __nv_bfloat16 g_wgp [(size_t)CINF * CINF];      // (wg;wphi)
__device__ __nv_bfloat16 g_wo  [(size_t)CINF * CINT];

// ------------------------- helpers ------------------------------------------
__device__ __forceinline__ uint32_t smem_u32(const void* p) {
    uint32_t a;
    asm("{ .reg .u64 t; cvta.to.shared.u64 t, %1; cvt.u32.u64 %0, t; }" : "=r"(a) : "l"(p));
    return a;
}
#define CP_ASYNC16(dst, src) \
    asm volatile("cp.async.cg.shared.global [%0], [%1], 16;" :: "r"(dst), "l"(src))
#define CP_ASYNC16Z(dst, src, sz) \
    asm volatile("cp.async.cg.shared.global [%0], [%1], 16, %2;" :: "r"(dst), "l"(src), "r"(sz))
#define CP_COMMIT() asm volatile("cp.async.commit_group;" ::: "memory")
#define CP_WAIT(n)  asm volatile("cp.async.wait_group %0;" :: "n"(n) : "memory")

#define LDSM4(r, a) \
    asm volatile("ldmatrix.sync.aligned.m8n8.x4.shared.b16 {%0,%1,%2,%3}, [%4];" \
        : "=r"((r)[0]), "=r"((r)[1]), "=r"((r)[2]), "=r"((r)[3]) : "r"(a))
#define LDSM4T(r, a) \
    asm volatile("ldmatrix.sync.aligned.m8n8.x4.trans.shared.b16 {%0,%1,%2,%3}, [%4];" \
        : "=r"((r)[0]), "=r"((r)[1]), "=r"((r)[2]), "=r"((r)[3]) : "r"(a))

#define MMA16816(d, a, bb0, bb1) \
    asm volatile("mma.sync.aligned.m16n8k16.row.col.f32.bf16.bf16.f32 " \
        "{%0,%1,%2,%3},{%4,%5,%6,%7},{%8,%9},{%0,%1,%2,%3};" \
        : "+f"((d)[0]), "+f"((d)[1]), "+f"((d)[2]), "+f"((d)[3]) \
        : "r"((a)[0]), "r"((a)[1]), "r"((a)[2]), "r"((a)[3]), "r"(bb0), "r"(bb1))

// 32-bf16-wide tile swizzle (64B rows, 4 x 16B chunks) — fused kernel phase 1
__device__ __forceinline__ uint32_t sw_off(int row, int ch) {
    return (uint32_t)(row * 64 + ((ch ^ ((row >> 1) & 3)) << 4));
}
// 64-bf16-wide tile swizzle (128B rows, 8 x 16B chunks) — GEMM stages
__device__ __forceinline__ uint32_t sw128(int row, int ch) {
    return (uint32_t)(row * 128 + ((ch ^ (row & 7)) << 4));
}

// ------------------------- transpose + convert (x & x_ref merged) ------------
// src [n][1024][PIX] fp32 -> dst [n][PIX][1024] bf16. Tile 32p x 64c.
__global__ void conv_tr2_k(const float* __restrict__ x, const float* __restrict__ xr,
                           __nv_bfloat16* __restrict__ dx, __nv_bfloat16* __restrict__ dxr)
{
    __shared__ float ts[64][33];
    const int tx = threadIdx.x, ty = threadIdx.y;
    const int z = blockIdx.z;
    const int n = z & (NB - 1);
    const float* src = (z < NB) ? x : xr;
    __nv_bfloat16* dst = (z < NB) ? dx : dxr;
    const int p0 = blockIdx.x * 32, c0 = blockIdx.y * 64;
    #pragma unroll
    for (int r = 0; r < 8; r++) {
        int cl = ty + r * 8;
        ts[cl][tx] = src[((size_t)n * CINF + c0 + cl) * PIX + p0 + tx];
    }
    __syncthreads();
    #pragma unroll
    for (int r = 0; r < 4; r++) {
        int pl = ty + r * 8;
        __nv_bfloat162 v = __floats2bfloat162_rn(ts[2 * tx][pl], ts[2 * tx + 1][pl]);
        *(__nv_bfloat162*)(dst + ((size_t)n * PIX + p0 + pl) * CINF + c0 + 2 * tx) = v;
    }
}

// all four weight tensors are 524288 elements each
__global__ void cvt4_k(const float* __restrict__ s0, const float* __restrict__ s1,
                       const float* __restrict__ s2, const float* __restrict__ s3,
                       __nv_bfloat16* __restrict__ d0, __nv_bfloat16* __restrict__ d1,
                       __nv_bfloat16* __restrict__ d2, __nv_bfloat16* __restrict__ d3)
{
    int i = blockIdx.x * 256 + threadIdx.x;
    int seg = i >> 19, off = i & 524287;
    const float* s = (seg == 0) ? s0 : (seg == 1) ? s1 : (seg == 2) ? s2 : s3;
    __nv_bfloat16* d = (seg == 0) ? d0 : (seg == 1) ? d1 : (seg == 2) ? d2 : d3;
    d[off] = __float2bfloat16(s[off]);
}

// ------------------------- merged projection GEMM ----------------------------
// blockIdx.y < 4 : theta = w_theta @ x   -> thb  [p][512]
// blockIdx.y >= 4: (g;phi) = wgp @ x_ref -> gphib [p][1024]
// 128x128 tile, K-chunk 64, 2-stage cp.async (64KB dyn smem), 8 warps.
__global__ __launch_bounds__(256)
void proj_gemm(const __nv_bfloat16* __restrict__ wth, const __nv_bfloat16* __restrict__ wgp,
               const __nv_bfloat16* __restrict__ xT, const __nv_bfloat16* __restrict__ xrT,
               const float* __restrict__ bth, const float* __restrict__ bg,
               const float* __restrict__ bphi,
               __nv_bfloat16* __restrict__ thb, __nv_bfloat16* __restrict__ gphib)
{
    extern __shared__ char smem[];   // 2 stages x (A 16KB | B 16KB)

    const int t = threadIdx.x, lane = t & 31, wid = t >> 5;
    const int warp_m = wid >> 2, warp_n = wid & 3;
    const int n = blockIdx.z, pbase = blockIdx.x * 128;
    const int by = blockIdx.y;
    const bool th = (by < 4);
    const int obase = (th ? by : by - 4) * 128;
    const __nv_bfloat16* A  = th ? wth : wgp;
    const __nv_bfloat16* Bx = th ? xT : xrT;
    __nv_bfloat16* out = th ? thb : gphib;
    const int ldo = th ? CINT : 2 * CINT;
    const float* b0 = th ? bth : bg;
    const float* b1 = th ? bth : bphi;
    const int K = CINF, NC = K >> 6;   // 16

    const __nv_bfloat16* Ab = A + (size_t)obase * K;
    const __nv_bfloat16* Bb = Bx + ((size_t)n * PIX + pbase) * K;
    const uint32_t sbase = smem_u32(smem);

    float acc[4][4][4];
    #pragma unroll
    for (int mi = 0; mi < 4; mi++)
        #pragma unroll
        for (int ni = 0; ni < 4; ni++)
            #pragma unroll
            for (int r = 0; r < 4; r++) acc[mi][ni][r] = 0.f;

    const int rowL = t >> 3, chL = t & 7;   // load mapping: 4 iters cover 128 rows
    auto issue = [&](int c) {
        const int k0 = c << 6;
        const uint32_t st = sbase + (c & 1) * 32768;
        #pragma unroll
        for (int i = 0; i < 4; i++) {
            int row = rowL + i * 32;
            CP_ASYNC16(st + sw128(row, chL), Ab + (size_t)row * K + k0 + chL * 8);
        }
        #pragma unroll
        for (int i = 0; i < 4; i++) {
            int row = rowL + i * 32;
            CP_ASYNC16(st + 16384 + sw128(row, chL), Bb + (size_t)row * K + k0 + chL * 8);
        }
        CP_COMMIT();
    };

    issue(0);
    const int rl = lane & 15, cs = lane >> 4;

    for (int c = 0; c < NC; c++) {
        CP_WAIT(0);
        __syncthreads();
        if (c + 1 < NC) issue(c + 1);

        const uint32_t stA = sbase + (c & 1) * 32768;
        const uint32_t stB = stA + 16384;
        #pragma unroll
        for (int kh = 0; kh < 4; kh++) {
            const int ch = 2 * kh + cs;
            uint32_t af[4][4], bf[2][4];
            #pragma unroll
            for (int mi = 0; mi < 4; mi++)
                LDSM4(af[mi], stA + sw128(warp_m * 64 + mi * 16 + rl, ch));
            #pragma unroll
            for (int g = 0; g < 2; g++)
                LDSM4(bf[g], stB + sw128(warp_n * 32 + g * 16 + rl, ch));
            #pragma unroll
            for (int mi = 0; mi < 4; mi++)
                #pragma unroll
                for (int g = 0; g < 2; g++) {
                    MMA16816(acc[mi][2 * g + 0], af[mi], bf[g][0], bf[g][2]);
                    MMA16816(acc[mi][2 * g + 1], af[mi], bf[g][1], bf[g][3]);
                }
        }
    }

    // epilogue: transpose via SMEM -> coalesced bf16 NHWC rows
    __syncthreads();
    __nv_bfloat16* S = (__nv_bfloat16*)smem;   // [128 p][136 o]
    #pragma unroll
    for (int mi = 0; mi < 4; mi++) {
        #pragma unroll
        for (int h = 0; h < 2; h++) {
            const int ol = warp_m * 64 + mi * 16 + (lane >> 2) + h * 8;
            const int og = obase + ol;
            const float bias = (og < CINT) ? b0[og] : b1[og - CINT];
            #pragma unroll
            for (int ni = 0; ni < 4; ni++) {
                const int pl = warp_n * 32 + ni * 8 + (lane & 3) * 2;
                S[(size_t)pl * 136 + ol]       = __float2bfloat16(acc[mi][ni][2 * h + 0] + bias);
                S[(size_t)(pl + 1) * 136 + ol] = __float2bfloat16(acc[mi][ni][2 * h + 1] + bias);
            }
        }
    }
    __syncthreads();
    #pragma unroll
    for (int s = 0; s < 16; s++) {
        const int pl = s * 8 + wid;
        uint2 v = *(uint2*)&S[(size_t)pl * 136 + lane * 4];
        *(uint2*)(out + ((size_t)n * PIX + pbase + pl) * ldo + obase + lane * 4) = v;
    }
}

// ------------------------- final GEMM (residual, fp32 NCHW) ------------------
// out[(n*CINF+o)*PIX + p] = sum_k wo[o][k]*y[p][k] + b[o] + resid[same]
__global__ __launch_bounds__(256)
void final_gemm(const __nv_bfloat16* __restrict__ A, const __nv_bfloat16* __restrict__ B,
                const float* __restrict__ b0, float* __restrict__ out,
                const float* __restrict__ resid)
{
    extern __shared__ char smem[];   // 2 stages x 32KB

    const int t = threadIdx.x, lane = t & 31, wid = t >> 5;
    const int warp_m = wid >> 2, warp_n = wid & 3;
    const int n = blockIdx.z, pbase = blockIdx.x * 128, obase = blockIdx.y * 128;
    const int K = CINT, NC = K >> 6;   // 8

    const __nv_bfloat16* Ab = A + (size_t)obase * K;
    const __nv_bfloat16* Bb = B + ((size_t)n * PIX + pbase) * K;
    const uint32_t sbase = smem_u32(smem);

    float acc[4][4][4];
    #pragma unroll
    for (int mi = 0; mi < 4; mi++)
        #pragma unroll
        for (int ni = 0; ni < 4; ni++)
            #pragma unroll
            for (int r = 0; r < 4; r++) acc[mi][ni][r] = 0.f;

    const int rowL = t >> 3, chL = t & 7;
    auto issue = [&](int c) {
        const int k0 = c << 6;
        const uint32_t st = sbase + (c & 1) * 32768;
        #pragma unroll
        for (int i = 0; i < 4; i++) {
            int row = rowL + i * 32;
            CP_ASYNC16(st + sw128(row, chL), Ab + (size_t)row * K + k0 + chL * 8);
        }
        #pragma unroll
        for (int i = 0; i < 4; i++) {
            int row = rowL + i * 32;
            CP_ASYNC16(st + 16384 + sw128(row, chL), Bb + (size_t)row * K + k0 + chL * 8);
        }
        CP_COMMIT();
    };

    issue(0);
    const int rl = lane & 15, cs = lane >> 4;

    for (int c = 0; c < NC; c++) {
        CP_WAIT(0);
        __syncthreads();
        if (c + 1 < NC) issue(c + 1);

        const uint32_t stA = sbase + (c & 1) * 32768;
        const uint32_t stB = stA + 16384;
        #pragma unroll
        for (int kh = 0; kh < 4; kh++) {
            const int ch = 2 * kh + cs;
            uint32_t af[4][4], bf[2][4];
            #pragma unroll
            for (int mi = 0; mi < 4; mi++)
                LDSM4(af[mi], stA + sw128(warp_m * 64 + mi * 16 + rl, ch));
            #pragma unroll
            for (int g = 0; g < 2; g++)
                LDSM4(bf[g], stB + sw128(warp_n * 32 + g * 16 + rl, ch));
            #pragma unroll
            for (int mi = 0; mi < 4; mi++)
                #pragma unroll
                for (int g = 0; g < 2; g++) {
                    MMA16816(acc[mi][2 * g + 0], af[mi], bf[g][0], bf[g][2]);
                    MMA16816(acc[mi][2 * g + 1], af[mi], bf[g][1], bf[g][3]);
                }
        }
    }

    // epilogue: stage to SMEM, then fully-coalesced resid add + store
    float* Es = (float*)smem;   // [64 o][132 p]
    #pragma unroll
    for (int og = 0; og < 2; og++) {
        __syncthreads();
        if (warp_m == og) {
            #pragma unroll
            for (int mi = 0; mi < 4; mi++)
                #pragma unroll
                for (int h = 0; h < 2; h++) {
                    const int row = mi * 16 + (lane >> 2) + h * 8;
                    #pragma unroll
                    for (int ni = 0; ni < 4; ni++) {
                        const int col = warp_n * 32 + ni * 8 + (lane & 3) * 2;
                        Es[(size_t)row * 132 + col]     = acc[mi][ni][2 * h + 0];
                        Es[(size_t)row * 132 + col + 1] = acc[mi][ni][2 * h + 1];
                    }
                }
        }
        __syncthreads();
        #pragma unroll
        for (int s = 0; s < 8; s++) {
            const int row = s * 8 + wid;
            const int o = obase + og * 64 + row;
            const size_t addr = ((size_t)n * CINF + o) * PIX + pbase + lane * 4;
            float4 e = *(float4*)&Es[(size_t)row * 132 + lane * 4];
            float4 r = *(const float4*)(resid + addr);
            const float bias = b0[o];
            float4 v;
            v.x = e.x + bias + r.x; v.y = e.y + bias + r.y;
            v.z = e.z + bias + r.z; v.w = e.w + bias + r.w;
            *(float4*)(out + addr) = v;
        }
    }
}

// ------------------------- fused corr + softmax + assemble -------------------
// Per 8x8 pixel tile (halo 16x16 = 256):
//   phase1: C[64][256] = theta_tile @ phi_halo^T  (tensor cores)
//   phase2: per-pixel softmax over its 81 halo cols -> PW bf16 [64][256] (+pad)
//   phase3: y[64][512] = PW @ g_halo              (tensor cores, B via ldmatrix.trans)
__global__ __launch_bounds__(256, 2)
void fused_attn_k(const __nv_bfloat16* __restrict__ theta,
                  const __nv_bfloat16* __restrict__ gphi,
                  __nv_bfloat16* __restrict__ y)
{
    extern __shared__ char smem[];
    char*  Xr   = smem + 33792;
    float* Cs   = (float*)Xr;                       // [64][266] fp32
    float* invs = (float*)(smem + 33792 + 68096);   // [64]

    const int t = threadIdx.x, lane = t & 31, wid = t >> 5;
    const int warp_m = wid >> 2, warp_n = wid & 3;  // 2 x 4
    const int rl = lane & 15, cs = lane >> 4;
    const int n = blockIdx.z, h0 = blockIdx.y * 8, w0 = blockIdx.x * 8;

    const uint32_t sbX  = smem_u32(Xr);
    const uint32_t sbPW = smem_u32(smem);

    float acc[2][8][4];
    #pragma unroll
    for (int a = 0; a < 2; a++)
        #pragma unroll
        for (int b = 0; b < 8; b++)
            #pragma unroll
            for (int c = 0; c < 4; c++) acc[a][b][c] = 0.f;

    // ---------------- phase 1: corr GEMM ----------------
    const int rowA = t >> 2, chA = t & 3;
    const __nv_bfloat16* thsrc =
        theta + ((size_t)n * PIX + (h0 + (rowA >> 3)) * WDIM + (w0 + (rowA & 7))) * CINT + chA * 8;

    const __nv_bfloat16* phsrc[4];
    uint32_t phok[4]; int phrow[4], phch[4];
    #pragma unroll
    for (int i = 0; i < 4; i++) {
        int idx = t + i * 256;
        int row = idx >> 2, ch = idx & 3;
        int hy = h0 + (row >> 4) - DD, hx = w0 + (row & 15) - DD;
        bool ok = (hy >= 0 && hy < HDIM && hx >= 0 && hx < WDIM);
        phrow[i] = row; phch[i] = ch; phok[i] = ok ? 16u : 0u;
        phsrc[i] = gphi + (ok ? (((size_t)n * PIX + hy * WDIM + hx) * 1024 + 512 + ch * 8) : 0);
    }

    auto issue1 = [&](int c) {
        const int c0 = c << 5;
        const uint32_t st = sbX + (c % 3) * 20480;
        CP_ASYNC16(st + sw_off(rowA, chA), thsrc + c0);
        #pragma unroll
        for (int i = 0; i < 4; i++)
            CP_ASYNC16Z(st + 4096 + sw_off(phrow[i], phch[i]),
                        phsrc[i] + (phok[i] ? c0 : 0), phok[i]);
        CP_COMMIT();
    };

    issue1(0); issue1(1);
    for (int c = 0; c < 16; c++) {
        if (c < 15) CP_WAIT(1); else CP_WAIT(0);
        __syncthreads();
        if (c + 2 < 16) issue1(c + 2);
        const uint32_t stA = sbX + (c % 3) * 20480;
        const uint32_t stB = stA + 4096;
        #pragma unroll
        for (int kh = 0; kh < 2; kh++) {
            const int ch = 2 * kh + cs;
            uint32_t af[2][4], bm[4][4];
            #pragma unroll
            for (int mi = 0; mi < 2; mi++)
                LDSM4(af[mi], stA + sw_off(warp_m * 32 + mi * 16 + rl, ch));
            #pragma unroll
            for (int nf = 0; nf < 4; nf++)
                LDSM4(bm[nf], stB + sw_off(warp_n * 64 + nf * 16 + rl, ch));
            #pragma unroll
            for (int mi = 0; mi < 2; mi++)
                #pragma unroll
                for (int nf = 0; nf < 4; nf++) {
                    MMA16816(acc[mi][2 * nf + 0], af[mi], bm[nf][0], bm[nf][2]);
                    MMA16816(acc[mi][2 * nf + 1], af[mi], bm[nf][1], bm[nf][3]);
                }
        }
    }
    __syncthreads();   // stages dead; write C to smem (overlays stage region)

    #pragma unroll
    for (int mi = 0; mi < 2; mi++)
        #pragma unroll
        for (int ni = 0; ni < 8; ni++) {
            const int r0  = warp_m * 32 + mi * 16 + (lane >> 2);
            const int col = warp_n * 64 + ni * 8 + 2 * (lane & 3);
            *(float2*)&Cs[(size_t)r0 * 266 + col]       = make_float2(acc[mi][ni][0], acc[mi][ni][1]);
            *(float2*)&Cs[(size_t)(r0 + 8) * 266 + col] = make_float2(acc[mi][ni][2], acc[mi][ni][3]);
        }
    __syncthreads();

    // ---------------- phase 2: softmax -> PW bf16 ----------------
    if (t < 64) {
        const int py = t >> 3, pxx = t & 7;
        uint32_t* pwz = (uint32_t*)(smem + t * 528);
        #pragma unroll 4
        for (int i = 0; i < 132; i++) pwz[i] = 0;
        const float SC = 0.051031036307982884f;   // 256/(512*sqrt(96))
        float m = -1e30f;
        #pragma unroll
        for (int dy = 0; dy < QD; dy++)
            #pragma unroll
            for (int dx = 0; dx < QD; dx++)
                m = fmaxf(m, Cs[(size_t)t * 266 + (py + dy) * 16 + pxx + dx] * SC);
        float s = 0.f;
        __nv_bfloat16* pwrow = (__nv_bfloat16*)(smem + t * 528);
        #pragma unroll
        for (int dy = 0; dy < QD; dy++)
            #pragma unroll
            for (int dx = 0; dx < QD; dx++) {
                const int col = (py + dy) * 16 + pxx + dx;
                float e = __expf(Cs[(size_t)t * 266 + col] * SC - m);
                s += e;
                pwrow[col] = __float2bfloat16(e);
            }
        invs[t] = 1.f / s;
    }
    __syncthreads();

    // ---------------- phase 3: assemble GEMM ----------------
    // Stage: 32 halo rows x 512B (32 x 16B chunks), swizzle chunk ^ (row & 7).
    for (int half = 0; half < 2; half++) {
        const int cbase = half * 256;
        #pragma unroll
        for (int a = 0; a < 2; a++)
            #pragma unroll
            for (int b = 0; b < 8; b++)
                #pragma unroll
                for (int c = 0; c < 4; c++) acc[a][b][c] = 0.f;

        auto issue3 = [&](int kk) {
            const uint32_t st = sbX + (kk % 3) * 16384;
            #pragma unroll
            for (int i = 0; i < 4; i++) {
                int idx = t + i * 256;
                int row = idx >> 5, ch = idx & 31;
                int hp = kk * 32 + row;
                int hy = h0 + (hp >> 4) - DD, hx = w0 + (hp & 15) - DD;
                bool ok = (hy >= 0 && hy < HDIM && hx >= 0 && hx < WDIM);
                const __nv_bfloat16* src = gphi +
                    (ok ? (((size_t)n * PIX + hy * WDIM + hx) * 1024 + cbase + ch * 8) : 0);
                CP_ASYNC16Z(st + row * 512 + ((ch ^ (row & 7)) << 4), src, ok ? 16u : 0u);
            }
            CP_COMMIT();
        };

        issue3(0); issue3(1);
        for (int kk = 0; kk < 8; kk++) {
            if (kk < 7) CP_WAIT(1); else CP_WAIT(0);
            __syncthreads();
            if (kk + 2 < 8) issue3(kk + 2);
            const uint32_t st = sbX + (kk % 3) * 16384;
            #pragma unroll
            for (int kh = 0; kh < 2; kh++) {
                uint32_t af[2][4], bm[4][4];
                const int chunk = kk * 4 + kh * 2 + cs;
                #pragma unroll
                for (int mi = 0; mi < 2; mi++)
                    LDSM4(af[mi], sbPW + (warp_m * 32 + mi * 16 + rl) * 528 + chunk * 16);
                const int r = kh * 16 + rl;
                #pragma unroll
                for (int nf = 0; nf < 4; nf++) {
                    const int c16 = warp_n * 8 + nf * 2 + cs;
                    LDSM4T(bm[nf], st + r * 512 + ((c16 ^ (r & 7)) << 4));
                }
                #pragma unroll
                for (int mi = 0; mi < 2; mi++)
                    #pragma unroll
                    for (int nf = 0; nf < 4; nf++) {
                        MMA16816(acc[mi][2 * nf + 0], af[mi], bm[nf][0], bm[nf][1]);
                        MMA16816(acc[mi][2 * nf + 1], af[mi], bm[nf][2], bm[nf][3]);
                    }
            }
        }

        #pragma unroll
        for (int mi = 0; mi < 2; mi++)
            #pragma unroll
            for (int ni = 0; ni < 8; ni++) {
                const int r0 = warp_m * 32 + mi * 16 + (lane >> 2);
                const int cc = cbase + warp_n * 64 + ni * 8 + 2 * (lane & 3);
                #pragma unroll
                for (int hh = 0; hh < 2; hh++) {
                    const int px = r0 + hh * 8;
                    const float is = invs[px];
                    const size_t addr =
                        ((size_t)n * PIX + (h0 + (px >> 3)) * WDIM + (w0 + (px & 7))) * CINT + cc;
                    __nv_bfloat162 pk = __floats2bfloat162_rn(acc[mi][ni][2 * hh + 0] * is,
                                                              acc[mi][ni][2 * hh + 1] * is);
                    *(__nv_bfloat162*)(y + addr) = pk;
                }
            }
        __syncthreads();
    }
}

// ---------------------------------------------------------------------------
extern "C" void kernel_launch(void* const* d_in, const int* in_sizes, int n_in,
                              void* d_out, int out_size)
{
    (void)in_sizes; (void)n_in; (void)out_size;
    const float* x       = (const float*)d_in[0];
    const float* x_ref   = (const float*)d_in[1];
    const float* w_g     = (const float*)d_in[2];
    const float* b_g     = (const float*)d_in[3];
    const float* w_theta = (const float*)d_in[4];
    const float* b_theta = (const float*)d_in[5];
    const float* w_phi   = (const float*)d_in[6];
    const float* b_phi   = (const float*)d_in[7];
    const float* w_out   = (const float*)d_in[8];
    const float* b_out   = (const float*)d_in[9];
    float* out = (float*)d_out;

    __nv_bfloat16 *xT_d, *xrT_d, *thb_d, *gphib_d, *ybf_d, *wth_d, *wgp_d, *wo_d;
    cudaGetSymbolAddress((void**)&xT_d,    g_xT);
    cudaGetSymbolAddress((void**)&xrT_d,   g_xrT);
    cudaGetSymbolAddress((void**)&thb_d,   g_thb);
    cudaGetSymbolAddress((void**)&gphib_d, g_gphib);
    cudaGetSymbolAddress((void**)&ybf_d,   g_ybf);
    cudaGetSymbolAddress((void**)&wth_d,   g_wth);
    cudaGetSymbolAddress((void**)&wgp_d,   g_wgp);
    cudaGetSymbolAddress((void**)&wo_d,    g_wo);

    const int FUSED_SMEM = 33792 + 68096 + 256;   // 102144
    const int GEMM_SMEM  = 2 * 32768;             // 65536
    cudaFuncSetAttribute(fused_attn_k, cudaFuncAttributeMaxDynamicSharedMemorySize, FUSED_SMEM);
    cudaFuncSetAttribute(proj_gemm,   cudaFuncAttributeMaxDynamicSharedMemorySize, GEMM_SMEM);
    cudaFuncSetAttribute(final_gemm,  cudaFuncAttributeMaxDynamicSharedMemorySize, GEMM_SMEM);

    // 1: all weight conversions in one launch
    cvt4_k<<<8192, 256>>>(w_theta, w_g, w_phi, w_out,
                          wth_d, wgp_d, wgp_d + (size_t)CINT * CINF, wo_d);

    // 2: transpose+convert both inputs NCHW fp32 -> [p][1024] bf16
    conv_tr2_k<<<dim3(PIX / 32, CINF / 64, 2 * NB), dim3(32, 8)>>>(x, x_ref, xT_d, xrT_d);

    // 3: merged theta + (g;phi) projections -> bf16 NHWC
    proj_gemm<<<dim3(72, 12, NB), 256, GEMM_SMEM>>>(
        wth_d, wgp_d, xT_d, xrT_d, b_theta, b_g, b_phi, thb_d, gphib_d);

    // 4: fused corr + softmax + assemble -> y bf16 [p][512]
    fused_attn_k<<<dim3(12, 12, NB), 256, FUSED_SMEM>>>(thb_d, gphib_d, ybf_d);

    // 5: out = x + w_out @ y + b_out (fp32 NCHW)
    final_gemm<<<dim3(72, 8, NB), 256, GEMM_SMEM>>>(wo_d, ybf_d, b_out, out, x);
}